// round 5
// baseline (speedup 1.0000x reference)
#include <cuda_runtime.h>
#include <cuda_bf16.h>
#include <cstdint>
#include <math.h>

// ---------------------------------------------------------------------------
// Mamba block forward. GEMMs via mma.sync (HMMA bf16 split hi/lo, fp32 accum).
// Big GEMMs use 256x128 CTA tiles (64x64 warp tiles); out_proj split-K=2.
// Scan on [channel][time]-transposed activations.
// ---------------------------------------------------------------------------

#define BATCH   2
#define SEQ     1024
#define DMODEL  1024
#define DINNER  2048
#define DSTATE  16
#define DTRANK  64
#define DCONV   4
#define NTOK    (BATCH * SEQ)
#define XPROJ_N (DTRANK + 2 * DSTATE)   // 96
#define XSPLIT  16
#define OSPLIT  2

typedef __nv_bfloat16 bf16;

// fp32 scratch
__device__ __align__(256) float g_xz[NTOK * 2 * DINNER];
__device__ __align__(256) float g_xsT[DINNER * NTOK];
__device__ __align__(256) float g_gT[DINNER * NTOK];
__device__ __align__(256) float g_dtT[DINNER * NTOK];
__device__ __align__(256) float g_bcT[2 * DSTATE * NTOK];
__device__ __align__(256) float g_yT[DINNER * NTOK];
__device__ __align__(256) float g_part[XSPLIT * NTOK * XPROJ_N];
__device__ __align__(256) float g_part2[OSPLIT * NTOK * DMODEL];

// bf16 hi/lo scratch
__device__ __align__(256) bf16 g_wih[2 * DINNER * DMODEL], g_wil[2 * DINNER * DMODEL];
__device__ __align__(256) bf16 g_wxh[XPROJ_N * DINNER],    g_wxl[XPROJ_N * DINNER];
__device__ __align__(256) bf16 g_wdh[DINNER * DTRANK],     g_wdl[DINNER * DTRANK];
__device__ __align__(256) bf16 g_woh[DMODEL * DINNER],     g_wol[DMODEL * DINNER];
__device__ __align__(256) bf16 g_hh[NTOK * DMODEL],        g_hl[NTOK * DMODEL];
__device__ __align__(256) bf16 g_xsh[NTOK * DINNER],       g_xsl[NTOK * DINNER];
__device__ __align__(256) bf16 g_xdh[NTOK * XPROJ_N],      g_xdl[NTOK * XPROJ_N];
__device__ __align__(256) bf16 g_yh[NTOK * DINNER],        g_yl[NTOK * DINNER];

// ---------------------------------------------------------------------------
// helpers
// ---------------------------------------------------------------------------
__device__ __forceinline__ uint32_t smem_u32(const void* p) {
    uint32_t a;
    asm("{ .reg .u64 t; cvta.to.shared.u64 t, %1; cvt.u32.u64 %0, t; }"
        : "=r"(a) : "l"(p));
    return a;
}
__device__ __forceinline__ void ldm_x4(uint32_t& r0, uint32_t& r1,
                                       uint32_t& r2, uint32_t& r3, uint32_t a) {
    asm volatile("ldmatrix.sync.aligned.m8n8.x4.shared.b16 {%0,%1,%2,%3}, [%4];"
                 : "=r"(r0), "=r"(r1), "=r"(r2), "=r"(r3) : "r"(a));
}
__device__ __forceinline__ void mma16816(float* d, const uint32_t* a,
                                         const uint32_t* b) {
    asm volatile(
        "mma.sync.aligned.m16n8k16.row.col.f32.bf16.bf16.f32 "
        "{%0,%1,%2,%3}, {%4,%5,%6,%7}, {%8,%9}, {%0,%1,%2,%3};"
        : "+f"(d[0]), "+f"(d[1]), "+f"(d[2]), "+f"(d[3])
        : "r"(a[0]), "r"(a[1]), "r"(a[2]), "r"(a[3]), "r"(b[0]), "r"(b[1]));
}
__device__ __forceinline__ void cp16(uint32_t dst, const void* src, int sz) {
    asm volatile("cp.async.cg.shared.global [%0], [%1], 16, %2;"
                 :: "r"(dst), "l"(src), "r"(sz) : "memory");
}
#define CP_COMMIT() asm volatile("cp.async.commit_group;" ::: "memory")
#define CP_WAIT(n)  asm volatile("cp.async.wait_group %0;" :: "n"(n) : "memory")

__device__ __forceinline__ uint32_t pack2(bf16 a, bf16 b) {
    return ((uint32_t)__bfloat16_as_ushort(b) << 16) | __bfloat16_as_ushort(a);
}
__device__ __forceinline__ void split1(float v, bf16& h, bf16& l) {
    h = __float2bfloat16(v);
    l = __float2bfloat16(v - __bfloat162float(h));
}
__device__ __forceinline__ void split4(float4 v, uint2& hi, uint2& lo) {
    bf16 h0, l0, h1, l1, h2, l2, h3, l3;
    split1(v.x, h0, l0); split1(v.y, h1, l1);
    split1(v.z, h2, l2); split1(v.w, h3, l3);
    hi.x = pack2(h0, h1); hi.y = pack2(h2, h3);
    lo.x = pack2(l0, l1); lo.y = pack2(l2, l3);
}
__device__ __forceinline__ float softplus_f(float v) {
    return (v > 15.f) ? v : log1pf(__expf(v));
}
__device__ __forceinline__ float silu_f(float v) {
    return v / (1.f + __expf(-v));
}

// ---------------------------------------------------------------------------
// Big HMMA GEMM: CTA 256x128, 8 warps of 64x64, K-chunk 64, double buffer.
// C[M,N] = A[M,K]·B[N,K]^T; split hi/lo, 3 passes. Plain fp32 store
// (optionally split-K via gridDim.z, partStride).
// ---------------------------------------------------------------------------
#define BSTAGE 98304
#define BIG_SMEM (2 * BSTAGE)   // 192 KB

__global__ void __launch_bounds__(256, 1) gemm_big(
    const bf16* __restrict__ Ah, const bf16* __restrict__ Al, int lda,
    const bf16* __restrict__ Bh, const bf16* __restrict__ Bl, int ldb,
    float* __restrict__ C, int ldc, int N, int Ksplit, long partStride)
{
    extern __shared__ char smem[];
    const uint32_t sb = smem_u32(smem);
    const int tid = threadIdx.x;
    const int bRow = blockIdx.y * 256, bCol = blockIdx.x * 128;
    const int kbase = blockIdx.z * Ksplit;
    C += (long)blockIdx.z * partStride;
    const int nChunks = Ksplit >> 6;

    const int wid = tid >> 5, l = tid & 31;
    const int wm = (wid >> 1) * 64, wn = (wid & 1) * 64;

    float acc[4][8][4];
    #pragma unroll
    for (int a = 0; a < 4; a++)
        #pragma unroll
        for (int b = 0; b < 8; b++)
            #pragma unroll
            for (int c = 0; c < 4; c++) acc[a][b][c] = 0.f;

    auto loadStage = [&](int c) {
        const int kt = kbase + (c << 6);
        const uint32_t base = sb + (c & 1) * BSTAGE;
        #pragma unroll
        for (int it = 0; it < 8; it++) {
            int lin = it * 256 + tid;          // 0..2047 : A 256 rows x 8 ch
            int row = lin >> 3, ch = lin & 7;
            uint32_t d = base + row * 128 + ((ch ^ (row & 7)) << 4);
            size_t aoff = (size_t)(bRow + row) * lda + kt + ch * 8;
            cp16(d,         Ah + aoff, 16);
            cp16(d + 32768, Al + aoff, 16);
        }
        #pragma unroll
        for (int it = 0; it < 4; it++) {
            int lin = it * 256 + tid;          // 0..1023 : B 128 rows x 8 ch
            int row = lin >> 3, ch = lin & 7;
            uint32_t d = base + 65536 + row * 128 + ((ch ^ (row & 7)) << 4);
            int bn = bCol + row;
            int ok = (bn < N) ? 16 : 0;
            size_t boff = (size_t)(bn < N ? bn : 0) * ldb + kt + ch * 8;
            cp16(d,         Bh + boff, ok);
            cp16(d + 16384, Bl + boff, ok);
        }
        CP_COMMIT();
    };

    loadStage(0);
    for (int c = 0; c < nChunks; c++) {
        if (c + 1 < nChunks) { loadStage(c + 1); CP_WAIT(1); }
        else                 { CP_WAIT(0); }
        __syncthreads();
        const uint32_t st = sb + (c & 1) * BSTAGE;

        const int hkA = l >> 4;
        const int matb = l >> 3;
        const int rB0 = (l & 7) + ((matb >> 1) << 3);
        const int hkB = matb & 1;

        #pragma unroll
        for (int ks = 0; ks < 4; ks++) {
            uint32_t Ahf[4][4], Alf[4][4];
            #pragma unroll
            for (int mi = 0; mi < 4; mi++) {
                int r = wm + mi * 16 + (l & 15);
                int ck = 2 * ks + hkA;
                uint32_t ad = st + r * 128 + ((ck ^ (r & 7)) << 4);
                ldm_x4(Ahf[mi][0], Ahf[mi][1], Ahf[mi][2], Ahf[mi][3], ad);
                ldm_x4(Alf[mi][0], Alf[mi][1], Alf[mi][2], Alf[mi][3], ad + 32768);
            }
            #pragma unroll
            for (int half = 0; half < 2; half++) {
                uint32_t Bhf[4][2], Blf[4][2];
                #pragma unroll
                for (int ng = 0; ng < 2; ng++) {
                    int r = wn + half * 32 + rB0 + ng * 16;
                    int ck = 2 * ks + hkB;
                    uint32_t ad = st + 65536 + r * 128 + ((ck ^ (r & 7)) << 4);
                    uint32_t t0, t1, t2, t3;
                    ldm_x4(t0, t1, t2, t3, ad);
                    Bhf[ng*2][0] = t0; Bhf[ng*2][1] = t1;
                    Bhf[ng*2+1][0] = t2; Bhf[ng*2+1][1] = t3;
                    ldm_x4(t0, t1, t2, t3, ad + 16384);
                    Blf[ng*2][0] = t0; Blf[ng*2][1] = t1;
                    Blf[ng*2+1][0] = t2; Blf[ng*2+1][1] = t3;
                }
                #pragma unroll
                for (int mi = 0; mi < 4; mi++)
                    #pragma unroll
                    for (int ni = 0; ni < 4; ni++) {
                        float* ac = acc[mi][half * 4 + ni];
                        mma16816(ac, Ahf[mi], Bhf[ni]);
                        mma16816(ac, Ahf[mi], Blf[ni]);
                        mma16816(ac, Alf[mi], Bhf[ni]);
                    }
            }
        }
        __syncthreads();
    }

    #pragma unroll
    for (int mi = 0; mi < 4; mi++) {
        #pragma unroll
        for (int h2 = 0; h2 < 2; h2++) {
            int row = bRow + wm + mi * 16 + h2 * 8 + (l >> 2);
            #pragma unroll
            for (int nj = 0; nj < 8; nj++) {
                int col = bCol + wn + nj * 8 + (l & 3) * 2;
                if (col < N) {
                    *reinterpret_cast<float2*>(C + (size_t)row * ldc + col) =
                        make_float2(acc[mi][nj][h2 * 2 + 0],
                                    acc[mi][nj][h2 * 2 + 1]);
                }
            }
        }
    }
}

// ---------------------------------------------------------------------------
// 128x128 HMMA GEMM (as round 4): EPI 0 none / 1 softplus+bias / 2 res.
// TRANS: transposed store.
// ---------------------------------------------------------------------------
#define STAGE_SZ 65536
#define GEMM_SMEM (2 * STAGE_SZ)

template<int EPI, int TRANS>
__global__ void __launch_bounds__(256, 1) mma_gemm(
    const bf16* __restrict__ Ah, const bf16* __restrict__ Al, int lda,
    const bf16* __restrict__ Bh, const bf16* __restrict__ Bl, int ldb,
    float* __restrict__ C, int ldc, int N, int Ksplit, long partStride,
    const float* __restrict__ bias, const float* __restrict__ res, int ldres)
{
    extern __shared__ char smem[];
    const uint32_t sb = smem_u32(smem);
    const int tid = threadIdx.x;
    const int bRow = blockIdx.y * 128, bCol = blockIdx.x * 128;
    const int kbase = blockIdx.z * Ksplit;
    C += (long)blockIdx.z * partStride;
    const int nChunks = Ksplit >> 6;

    const int wid = tid >> 5, l = tid & 31;
    const int wm = (wid >> 2) * 64, wn = (wid & 3) * 32;

    float acc[4][4][4];
    #pragma unroll
    for (int a = 0; a < 4; a++)
        #pragma unroll
        for (int b = 0; b < 4; b++)
            #pragma unroll
            for (int c = 0; c < 4; c++) acc[a][b][c] = 0.f;

    auto loadStage = [&](int c) {
        const int kt = kbase + (c << 6);
        const uint32_t base = sb + (c & 1) * STAGE_SZ;
        #pragma unroll
        for (int it = 0; it < 4; it++) {
            int lin = it * 256 + tid;
            int row = lin >> 3, ch = lin & 7;
            uint32_t d = base + row * 128 + (((ch ^ (row & 7)) << 4));
            size_t aoff = (size_t)(bRow + row) * lda + kt + ch * 8;
            cp16(d,         Ah + aoff, 16);
            cp16(d + 16384, Al + aoff, 16);
            int bn = bCol + row;
            int ok = (bn < N) ? 16 : 0;
            size_t boff = (size_t)(bn < N ? bn : 0) * ldb + kt + ch * 8;
            cp16(d + 32768, Bh + boff, ok);
            cp16(d + 49152, Bl + boff, ok);
        }
        CP_COMMIT();
    };

    loadStage(0);
    for (int c = 0; c < nChunks; c++) {
        if (c + 1 < nChunks) { loadStage(c + 1); CP_WAIT(1); }
        else                 { CP_WAIT(0); }
        __syncthreads();
        const uint32_t st = sb + (c & 1) * STAGE_SZ;

        uint32_t baseA[4]; int r7A[4];
        #pragma unroll
        for (int mi = 0; mi < 4; mi++) {
            int r = wm + mi * 16 + (l & 15);
            baseA[mi] = st + r * 128;
            r7A[mi] = r & 7;
        }
        const int hkA = l >> 4;
        const int matb = l >> 3;
        const int rB0 = wn + (l & 7) + ((matb >> 1) << 3);
        const int hkB = matb & 1;

        #pragma unroll
        for (int ks = 0; ks < 4; ks++) {
            uint32_t Ahf[4][4], Alf[4][4], Bhf[4][2], Blf[4][2];
            #pragma unroll
            for (int mi = 0; mi < 4; mi++) {
                int ck = 2 * ks + hkA;
                uint32_t ad = baseA[mi] + ((ck ^ r7A[mi]) << 4);
                ldm_x4(Ahf[mi][0], Ahf[mi][1], Ahf[mi][2], Ahf[mi][3], ad);
                ldm_x4(Alf[mi][0], Alf[mi][1], Alf[mi][2], Alf[mi][3], ad + 16384);
            }
            #pragma unroll
            for (int ng = 0; ng < 2; ng++) {
                int r = rB0 + ng * 16;
                int ck = 2 * ks + hkB;
                uint32_t ad = st + 32768 + r * 128 + ((ck ^ (r & 7)) << 4);
                uint32_t t0, t1, t2, t3;
                ldm_x4(t0, t1, t2, t3, ad);
                Bhf[ng*2][0] = t0; Bhf[ng*2][1] = t1;
                Bhf[ng*2+1][0] = t2; Bhf[ng*2+1][1] = t3;
                ldm_x4(t0, t1, t2, t3, ad + 16384);
                Blf[ng*2][0] = t0; Blf[ng*2][1] = t1;
                Blf[ng*2+1][0] = t2; Blf[ng*2+1][1] = t3;
            }
            #pragma unroll
            for (int mi = 0; mi < 4; mi++)
                #pragma unroll
                for (int ni = 0; ni < 4; ni++) {
                    mma16816(acc[mi][ni], Ahf[mi], Bhf[ni]);
                    mma16816(acc[mi][ni], Ahf[mi], Blf[ni]);
                    mma16816(acc[mi][ni], Alf[mi], Bhf[ni]);
                }
        }
        __syncthreads();
    }

    #pragma unroll
    for (int mi = 0; mi < 4; mi++) {
        #pragma unroll
        for (int h2 = 0; h2 < 2; h2++) {
            int row = bRow + wm + mi * 16 + h2 * 8 + (l >> 2);
            #pragma unroll
            for (int ni = 0; ni < 4; ni++) {
                int col = bCol + wn + ni * 8 + (l & 3) * 2;
                if (col < N) {
                    float v0 = acc[mi][ni][h2 * 2 + 0];
                    float v1 = acc[mi][ni][h2 * 2 + 1];
                    if (EPI == 1) {
                        v0 = softplus_f(v0 + bias[col]);
                        v1 = softplus_f(v1 + bias[col + 1]);
                    } else if (EPI == 2) {
                        const float* rr = res + (size_t)row * ldres + col;
                        v0 += rr[0]; v1 += rr[1];
                    }
                    if (TRANS) {
                        C[(size_t)col * ldc + row] = v0;
                        C[(size_t)(col + 1) * ldc + row] = v1;
                    } else {
                        *reinterpret_cast<float2*>(C + (size_t)row * ldc + col) =
                            make_float2(v0, v1);
                    }
                }
            }
        }
    }
}

// ---------------------------------------------------------------------------
// weight fp32 -> bf16 hi/lo
// ---------------------------------------------------------------------------
__global__ __launch_bounds__(256) void convert_w(
    const float* __restrict__ w, bf16* __restrict__ hi, bf16* __restrict__ lo,
    int n4)
{
    int i = blockIdx.x * 256 + threadIdx.x;
    if (i >= n4) return;
    float4 v = reinterpret_cast<const float4*>(w)[i];
    uint2 h, l;
    split4(v, h, l);
    reinterpret_cast<uint2*>(hi)[i] = h;
    reinterpret_cast<uint2*>(lo)[i] = l;
}

// ---------------------------------------------------------------------------
// RMSNorm -> bf16 hi/lo
// ---------------------------------------------------------------------------
__global__ __launch_bounds__(256) void rmsnorm_kernel(
    const float* __restrict__ x, const float* __restrict__ w,
    bf16* __restrict__ hh, bf16* __restrict__ hl)
{
    int row = blockIdx.x;
    int tid = threadIdx.x;
    float4 v = reinterpret_cast<const float4*>(x + (size_t)row * DMODEL)[tid];
    float ss = v.x * v.x + v.y * v.y + v.z * v.z + v.w * v.w;
    __shared__ float red[8];
    #pragma unroll
    for (int o = 16; o > 0; o >>= 1) ss += __shfl_xor_sync(0xffffffffu, ss, o);
    if ((tid & 31) == 0) red[tid >> 5] = ss;
    __syncthreads();
    if (tid < 32) {
        float t = (tid < 8) ? red[tid] : 0.f;
        #pragma unroll
        for (int o = 4; o > 0; o >>= 1) t += __shfl_xor_sync(0xffffffffu, t, o);
        if (tid == 0) red[0] = t;
    }
    __syncthreads();
    float scale = rsqrtf(red[0] * (1.0f / DMODEL) + 1e-5f);
    float4 wv = reinterpret_cast<const float4*>(w)[tid];
    float4 o;
    o.x = v.x * scale * wv.x;  o.y = v.y * scale * wv.y;
    o.z = v.z * scale * wv.z;  o.w = v.w * scale * wv.w;
    uint2 h, l;
    split4(o, h, l);
    reinterpret_cast<uint2*>(hh + (size_t)row * DMODEL)[tid] = h;
    reinterpret_cast<uint2*>(hl + (size_t)row * DMODEL)[tid] = l;
}

// ---------------------------------------------------------------------------
// conv(width4)+SiLU + silu(z)
// ---------------------------------------------------------------------------
__global__ __launch_bounds__(256) void conv_silu_kernel(
    const float* __restrict__ xz,
    const float* __restrict__ conv_w, const float* __restrict__ conv_b,
    bf16* __restrict__ xsh, bf16* __restrict__ xsl,
    float* __restrict__ xsT, float* __restrict__ gT)
{
    int gid = blockIdx.x * 256 + threadIdx.x;
    if (gid >= NTOK * (DINNER / 4)) return;
    int trow = gid / (DINNER / 4);
    int d0 = (gid % (DINNER / 4)) * 4;
    int lpos = trow & (SEQ - 1);

    float4 accv = *reinterpret_cast<const float4*>(conv_b + d0);
    float* acc = &accv.x;
    #pragma unroll
    for (int k = 0; k < DCONV; k++) {
        int li = lpos + k - (DCONV - 1);
        if (li >= 0) {
            const float* xp = xz + (size_t)(trow + li - lpos) * (2 * DINNER) + d0;
            #pragma unroll
            for (int q = 0; q < 4; q++)
                acc[q] = fmaf(conv_w[(d0 + q) * DCONV + k], xp[q], acc[q]);
        }
    }
    #pragma unroll
    for (int q = 0; q < 4; q++) acc[q] = silu_f(acc[q]);
    size_t base = (size_t)trow * DINNER + d0;
    uint2 h, l;
    split4(accv, h, l);
    *reinterpret_cast<uint2*>(xsh + base) = h;
    *reinterpret_cast<uint2*>(xsl + base) = l;

    float4 zv = *reinterpret_cast<const float4*>(
        xz + (size_t)trow * (2 * DINNER) + DINNER + d0);
    const float* zz = &zv.x;
    #pragma unroll
    for (int q = 0; q < 4; q++) {
        xsT[(size_t)(d0 + q) * NTOK + trow] = acc[q];
        gT[(size_t)(d0 + q) * NTOK + trow] = silu_f(zz[q]);
    }
}

// ---------------------------------------------------------------------------
// split-K reduce for x_proj
// ---------------------------------------------------------------------------
__global__ __launch_bounds__(256) void reduce_xproj(
    const float* __restrict__ part,
    bf16* __restrict__ xdh, bf16* __restrict__ xdl,
    float* __restrict__ bcT)
{
    int idx = blockIdx.x * 256 + threadIdx.x;
    if (idx >= NTOK * XPROJ_N) return;
    float s = 0.f;
    #pragma unroll
    for (int z = 0; z < XSPLIT; z++) s += part[(size_t)z * NTOK * XPROJ_N + idx];
    bf16 h, l;
    split1(s, h, l);
    xdh[idx] = h; xdl[idx] = l;
    int row = idx / XPROJ_N, col = idx - row * XPROJ_N;
    if (col >= DTRANK)
        bcT[(size_t)(col - DTRANK) * NTOK + row] = s;
}

// ---------------------------------------------------------------------------
// split-K reduce for out_proj + residual -> final output
// ---------------------------------------------------------------------------
__global__ __launch_bounds__(256) void reduce_out(
    const float* __restrict__ part, const float* __restrict__ res,
    float* __restrict__ out)
{
    int i = blockIdx.x * 256 + threadIdx.x;   // float4 index
    if (i >= NTOK * DMODEL / 4) return;
    float4 a = reinterpret_cast<const float4*>(part)[i];
    float4 b = reinterpret_cast<const float4*>(part + (size_t)NTOK * DMODEL)[i];
    float4 r = reinterpret_cast<const float4*>(res)[i];
    float4 o;
    o.x = a.x + b.x + r.x;  o.y = a.y + b.y + r.y;
    o.z = a.z + b.z + r.z;  o.w = a.w + b.w + r.w;
    reinterpret_cast<float4*>(out)[i] = o;
}

// ---------------------------------------------------------------------------
// selective scan + gate (transposed, float4 pipeline)
// ---------------------------------------------------------------------------
__global__ __launch_bounds__(256) void scan_kernel(
    const float* __restrict__ dtT, const float* __restrict__ xsT,
    const float* __restrict__ bcT, const float* __restrict__ gT,
    const float* __restrict__ A_log, const float* __restrict__ Dp,
    float* __restrict__ yT)
{
    int warp = threadIdx.x >> 5;
    int lane = threadIdx.x & 31;
    int chPair = blockIdx.x * 8 + warp;
    int ch = chPair * 2 + (lane >> 4);
    int b = ch >> 11;
    int d = ch & 2047;
    int n = lane & 15;
    int rowBase = b * SEQ;

    const float* dtp = dtT + (size_t)d * NTOK + rowBase;
    const float* xsp = xsT + (size_t)d * NTOK + rowBase;
    const float* gp  = gT  + (size_t)d * NTOK + rowBase;
    const float* Bp  = bcT + (size_t)n * NTOK + rowBase;
    const float* Cp  = bcT + (size_t)(DSTATE + n) * NTOK + rowBase;
    float* yp = yT + (size_t)d * NTOK + rowBase;

    float a  = -expf(A_log[d * DSTATE + n]);
    float Dv = Dp[d];
    float s = 0.f;

    float4 dt4 = *reinterpret_cast<const float4*>(dtp);
    float4 xs4 = *reinterpret_cast<const float4*>(xsp);
    float4 g4  = *reinterpret_cast<const float4*>(gp);
    float4 B4  = *reinterpret_cast<const float4*>(Bp);
    float4 C4  = *reinterpret_cast<const float4*>(Cp);

    for (int t = 0; t < SEQ; t += 4) {
        float4 ndt, nxs, ng, nB, nC;
        if (t + 4 < SEQ) {
            ndt = *reinterpret_cast<const float4*>(dtp + t + 4);
            nxs = *reinterpret_cast<const float4*>(xsp + t + 4);
            ng  = *reinterpret_cast<const float4*>(gp + t + 4);
            nB  = *reinterpret_cast<const float4*>(Bp + t + 4);
            nC  = *reinterpret_cast<const float4*>(Cp + t + 4);
        }
        const float* dtv = &dt4.x; const float* xsv = &xs4.x;
        const float* gv = &g4.x; const float* Bv = &B4.x; const float* Cv = &C4.x;
        float4 yout;
        float* yv = &yout.x;
        #pragma unroll
        for (int q = 0; q < 4; q++) {
            float dA = __expf(dtv[q] * a);
            s = fmaf(dA, s, dtv[q] * xsv[q] * Bv[q]);
            float p = s * Cv[q];
            p += __shfl_xor_sync(0xffffffffu, p, 8);
            p += __shfl_xor_sync(0xffffffffu, p, 4);
            p += __shfl_xor_sync(0xffffffffu, p, 2);
            p += __shfl_xor_sync(0xffffffffu, p, 1);
            yv[q] = (p + Dv * xsv[q]) * gv[q];
        }
        if (n == 0)
            *reinterpret_cast<float4*>(yp + t) = yout;
        dt4 = ndt; xs4 = nxs; g4 = ng; B4 = nB; C4 = nC;
    }
}

// ---------------------------------------------------------------------------
// yT fp32 -> y bf16 hi/lo (tiled transpose)
// ---------------------------------------------------------------------------
__global__ __launch_bounds__(256) void transpose_split(
    const float* __restrict__ yT, bf16* __restrict__ yh, bf16* __restrict__ yl)
{
    __shared__ float tile[32][33];
    int bx = blockIdx.x, by = blockIdx.y;
    int tx = threadIdx.x & 31, ty = threadIdx.x >> 5;
    #pragma unroll
    for (int j = 0; j < 32; j += 8) {
        int dd = by * 32 + ty + j;
        int tok = bx * 32 + tx;
        tile[ty + j][tx] = yT[(size_t)dd * NTOK + tok];
    }
    __syncthreads();
    #pragma unroll
    for (int j = 0; j < 32; j += 8) {
        int tok = bx * 32 + ty + j;
        int dd = by * 32 + tx;
        float v = tile[tx][ty + j];
        bf16 h, l;
        split1(v, h, l);
        yh[(size_t)tok * DINNER + dd] = h;
        yl[(size_t)tok * DINNER + dd] = l;
    }
}

// ---------------------------------------------------------------------------
// Launch
// ---------------------------------------------------------------------------
extern "C" void kernel_launch(void* const* d_in, const int* in_sizes, int n_in,
                              void* d_out, int out_size)
{
    const float* x         = (const float*)d_in[0];
    const float* norm_w    = (const float*)d_in[1];
    const float* in_proj_w = (const float*)d_in[2];
    const float* conv_w    = (const float*)d_in[3];
    const float* conv_b    = (const float*)d_in[4];
    const float* x_proj_w  = (const float*)d_in[5];
    const float* dt_proj_w = (const float*)d_in[6];
    const float* dt_proj_b = (const float*)d_in[7];
    const float* A_log     = (const float*)d_in[8];
    const float* Dp        = (const float*)d_in[9];
    const float* out_proj_w= (const float*)d_in[10];
    float* out = (float*)d_out;

    float *pxz, *pxsT, *pgT, *pdtT, *pbcT, *pyT, *ppart, *ppart2;
    bf16 *pwih, *pwil, *pwxh, *pwxl, *pwdh, *pwdl, *pwoh, *pwol;
    bf16 *phh, *phl, *pxsh, *pxsl, *pxdh, *pxdl, *pyh, *pyl;
    cudaGetSymbolAddress((void**)&pxz,  g_xz);
    cudaGetSymbolAddress((void**)&pxsT, g_xsT);
    cudaGetSymbolAddress((void**)&pgT,  g_gT);
    cudaGetSymbolAddress((void**)&pdtT, g_dtT);
    cudaGetSymbolAddress((void**)&pbcT, g_bcT);
    cudaGetSymbolAddress((void**)&pyT,  g_yT);
    cudaGetSymbolAddress((void**)&ppart,g_part);
    cudaGetSymbolAddress((void**)&ppart2,g_part2);
    cudaGetSymbolAddress((void**)&pwih, g_wih); cudaGetSymbolAddress((void**)&pwil, g_wil);
    cudaGetSymbolAddress((void**)&pwxh, g_wxh); cudaGetSymbolAddress((void**)&pwxl, g_wxl);
    cudaGetSymbolAddress((void**)&pwdh, g_wdh); cudaGetSymbolAddress((void**)&pwdl, g_wdl);
    cudaGetSymbolAddress((void**)&pwoh, g_woh); cudaGetSymbolAddress((void**)&pwol, g_wol);
    cudaGetSymbolAddress((void**)&phh,  g_hh);  cudaGetSymbolAddress((void**)&phl,  g_hl);
    cudaGetSymbolAddress((void**)&pxsh, g_xsh); cudaGetSymbolAddress((void**)&pxsl, g_xsl);
    cudaGetSymbolAddress((void**)&pxdh, g_xdh); cudaGetSymbolAddress((void**)&pxdl, g_xdl);
    cudaGetSymbolAddress((void**)&pyh,  g_yh);  cudaGetSymbolAddress((void**)&pyl,  g_yl);

    cudaFuncSetAttribute(gemm_big, cudaFuncAttributeMaxDynamicSharedMemorySize, BIG_SMEM);
    cudaFuncSetAttribute(mma_gemm<0,0>, cudaFuncAttributeMaxDynamicSharedMemorySize, GEMM_SMEM);
    cudaFuncSetAttribute(mma_gemm<1,1>, cudaFuncAttributeMaxDynamicSharedMemorySize, GEMM_SMEM);

    // 0) weight conversion
    convert_w<<<(2*DINNER*DMODEL/4 + 255)/256, 256>>>(in_proj_w,  pwih, pwil, 2*DINNER*DMODEL/4);
    convert_w<<<(XPROJ_N*DINNER/4 + 255)/256, 256>>>(x_proj_w,   pwxh, pwxl, XPROJ_N*DINNER/4);
    convert_w<<<(DINNER*DTRANK/4 + 255)/256, 256>>>(dt_proj_w,  pwdh, pwdl, DINNER*DTRANK/4);
    convert_w<<<(DMODEL*DINNER/4 + 255)/256, 256>>>(out_proj_w, pwoh, pwol, DMODEL*DINNER/4);

    // 1) RMSNorm
    rmsnorm_kernel<<<NTOK, 256>>>(x, norm_w, phh, phl);

    // 2) in_proj: 256x128 tiles -> grid (32, 8)
    {
        dim3 grid((2 * DINNER) / 128, NTOK / 256, 1);
        gemm_big<<<grid, 256, BIG_SMEM>>>(
            phh, phl, DMODEL, pwih, pwil, DMODEL,
            pxz, 2 * DINNER, 2 * DINNER, DMODEL, 0);
    }

    // 3) conv + silu
    conv_silu_kernel<<<(NTOK * DINNER / 4) / 256, 256>>>(
        pxz, conv_w, conv_b, pxsh, pxsl, pxsT, pgT);

    // 4) x_proj split-K
    {
        dim3 grid(1, NTOK / 128, XSPLIT);
        mma_gemm<0,0><<<grid, 256, GEMM_SMEM>>>(
            pxsh, pxsl, DINNER, pwxh, pwxl, DINNER,
            ppart, XPROJ_N, XPROJ_N, DINNER / XSPLIT,
            (long)NTOK * XPROJ_N, nullptr, nullptr, 0);
    }
    reduce_xproj<<<(NTOK * XPROJ_N + 255) / 256, 256>>>(ppart, pxdh, pxdl, pbcT);

    // 5) dt_proj + softplus (transposed store)
    {
        dim3 grid(DINNER / 128, NTOK / 128, 1);
        mma_gemm<1,1><<<grid, 256, GEMM_SMEM>>>(
            pxdh, pxdl, XPROJ_N, pwdh, pwdl, DTRANK,
            pdtT, NTOK, DINNER, DTRANK, 0, dt_proj_b, nullptr, 0);
    }

    // 6) scan -> yT
    scan_kernel<<<(BATCH * DINNER) / 16, 256>>>(pdtT, pxsT, pbcT, pgT,
                                                A_log, Dp, pyT);

    // 7) transpose + split y
    {
        dim3 grid(NTOK / 32, DINNER / 32);
        transpose_split<<<grid, 256>>>(pyT, pyh, pyl);
    }

    // 8) out_proj split-K=2 (256x128 tiles): grid (8, 8, 2)
    {
        dim3 grid(DMODEL / 128, NTOK / 256, OSPLIT);
        gemm_big<<<grid, 256, BIG_SMEM>>>(
            pyh, pyl, DINNER, pwoh, pwol, DINNER,
            ppart2, DMODEL, DMODEL, DINNER / OSPLIT,
            (long)NTOK * DMODEL);
    }
    reduce_out<<<(NTOK * DMODEL / 4 + 255) / 256, 256>>>(ppart2, x, out);
}

// round 6
// speedup vs baseline: 1.7910x; 1.7910x over previous
#include <cuda_runtime.h>
#include <cuda_bf16.h>
#include <cstdint>
#include <math.h>

// ---------------------------------------------------------------------------
// Mamba block forward. GEMMs via mma.sync (HMMA bf16 split hi/lo, fp32 accum),
// 128x128 CTA tiles, 3-stage cp.async pipeline. Scan on transposed layout.
// ---------------------------------------------------------------------------

#define BATCH   2
#define SEQ     1024
#define DMODEL  1024
#define DINNER  2048
#define DSTATE  16
#define DTRANK  64
#define DCONV   4
#define NTOK    (BATCH * SEQ)
#define XPROJ_N (DTRANK + 2 * DSTATE)   // 96
#define XSPLIT  16

typedef __nv_bfloat16 bf16;

// fp32 scratch
__device__ __align__(256) float g_xz[NTOK * 2 * DINNER];
__device__ __align__(256) float g_xsT[DINNER * NTOK];
__device__ __align__(256) float g_gT[DINNER * NTOK];
__device__ __align__(256) float g_dtT[DINNER * NTOK];
__device__ __align__(256) float g_bcT[2 * DSTATE * NTOK];
__device__ __align__(256) float g_yT[DINNER * NTOK];
__device__ __align__(256) float g_part[XSPLIT * NTOK * XPROJ_N];

// bf16 hi/lo scratch
__device__ __align__(256) bf16 g_wih[2 * DINNER * DMODEL], g_wil[2 * DINNER * DMODEL];
__device__ __align__(256) bf16 g_wxh[XPROJ_N * DINNER],    g_wxl[XPROJ_N * DINNER];
__device__ __align__(256) bf16 g_wdh[DINNER * DTRANK],     g_wdl[DINNER * DTRANK];
__device__ __align__(256) bf16 g_woh[DMODEL * DINNER],     g_wol[DMODEL * DINNER];
__device__ __align__(256) bf16 g_hh[NTOK * DMODEL],        g_hl[NTOK * DMODEL];
__device__ __align__(256) bf16 g_xsh[NTOK * DINNER],       g_xsl[NTOK * DINNER];
__device__ __align__(256) bf16 g_xdh[NTOK * XPROJ_N],      g_xdl[NTOK * XPROJ_N];
__device__ __align__(256) bf16 g_yh[NTOK * DINNER],        g_yl[NTOK * DINNER];

// ---------------------------------------------------------------------------
// helpers
// ---------------------------------------------------------------------------
__device__ __forceinline__ uint32_t smem_u32(const void* p) {
    uint32_t a;
    asm("{ .reg .u64 t; cvta.to.shared.u64 t, %1; cvt.u32.u64 %0, t; }"
        : "=r"(a) : "l"(p));
    return a;
}
__device__ __forceinline__ void ldm_x4(uint32_t& r0, uint32_t& r1,
                                       uint32_t& r2, uint32_t& r3, uint32_t a) {
    asm volatile("ldmatrix.sync.aligned.m8n8.x4.shared.b16 {%0,%1,%2,%3}, [%4];"
                 : "=r"(r0), "=r"(r1), "=r"(r2), "=r"(r3) : "r"(a));
}
__device__ __forceinline__ void mma16816(float* d, const uint32_t* a,
                                         const uint32_t* b) {
    asm volatile(
        "mma.sync.aligned.m16n8k16.row.col.f32.bf16.bf16.f32 "
        "{%0,%1,%2,%3}, {%4,%5,%6,%7}, {%8,%9}, {%0,%1,%2,%3};"
        : "+f"(d[0]), "+f"(d[1]), "+f"(d[2]), "+f"(d[3])
        : "r"(a[0]), "r"(a[1]), "r"(a[2]), "r"(a[3]), "r"(b[0]), "r"(b[1]));
}
__device__ __forceinline__ void cp16(uint32_t dst, const void* src, int sz) {
    asm volatile("cp.async.cg.shared.global [%0], [%1], 16, %2;"
                 :: "r"(dst), "l"(src), "r"(sz) : "memory");
}
#define CP_COMMIT() asm volatile("cp.async.commit_group;" ::: "memory")
#define CP_WAIT(n)  asm volatile("cp.async.wait_group %0;" :: "n"(n) : "memory")

__device__ __forceinline__ uint32_t pack2(bf16 a, bf16 b) {
    return ((uint32_t)__bfloat16_as_ushort(b) << 16) | __bfloat16_as_ushort(a);
}
__device__ __forceinline__ void split1(float v, bf16& h, bf16& l) {
    h = __float2bfloat16(v);
    l = __float2bfloat16(v - __bfloat162float(h));
}
__device__ __forceinline__ void split4(float4 v, uint2& hi, uint2& lo) {
    bf16 h0, l0, h1, l1, h2, l2, h3, l3;
    split1(v.x, h0, l0); split1(v.y, h1, l1);
    split1(v.z, h2, l2); split1(v.w, h3, l3);
    hi.x = pack2(h0, h1); hi.y = pack2(h2, h3);
    lo.x = pack2(l0, l1); lo.y = pack2(l2, l3);
}
__device__ __forceinline__ float softplus_f(float v) {
    return (v > 15.f) ? v : log1pf(__expf(v));
}
__device__ __forceinline__ float silu_f(float v) {
    return v / (1.f + __expf(-v));
}

// ---------------------------------------------------------------------------
// HMMA GEMM (NT): C[M,N] = A[M,K]·B[N,K]^T, split hi+lo bf16, fp32 accum.
// CTA 128x128, 8 warps of 64x32, K-chunk 64, 3-stage cp.async pipeline.
// EPI: 0 none, 1 softplus(acc+bias[n]), 2 acc+res[m,n].
// TRANS: 1 -> coalesced transposed store via smem staging.
// ---------------------------------------------------------------------------
#define STAGE_SZ 65536
#define NSTAGE 3
#define GEMM_SMEM (NSTAGE * STAGE_SZ)   // 192 KB

template<int EPI, int TRANS>
__global__ void __launch_bounds__(256, 1) mma_gemm(
    const bf16* __restrict__ Ah, const bf16* __restrict__ Al, int lda,
    const bf16* __restrict__ Bh, const bf16* __restrict__ Bl, int ldb,
    float* __restrict__ C, int ldc, int N, int Ksplit, long partStride,
    const float* __restrict__ bias, const float* __restrict__ res, int ldres)
{
    extern __shared__ char smem[];
    const uint32_t sb = smem_u32(smem);
    const int tid = threadIdx.x;
    const int bRow = blockIdx.y * 128, bCol = blockIdx.x * 128;
    const int kbase = blockIdx.z * Ksplit;
    C += (long)blockIdx.z * partStride;
    const int nChunks = Ksplit >> 6;

    const int wid = tid >> 5, l = tid & 31;
    const int wm = (wid >> 2) * 64, wn = (wid & 3) * 32;

    float acc[4][4][4];
    #pragma unroll
    for (int a = 0; a < 4; a++)
        #pragma unroll
        for (int b = 0; b < 4; b++)
            #pragma unroll
            for (int c = 0; c < 4; c++) acc[a][b][c] = 0.f;

    auto loadStage = [&](int c) {
        const int kt = kbase + (c << 6);
        const uint32_t base = sb + (c % NSTAGE) * STAGE_SZ;
        #pragma unroll
        for (int it = 0; it < 4; it++) {
            int lin = it * 256 + tid;
            int row = lin >> 3, ch = lin & 7;
            uint32_t d = base + row * 128 + (((ch ^ (row & 7)) << 4));
            size_t aoff = (size_t)(bRow + row) * lda + kt + ch * 8;
            cp16(d,         Ah + aoff, 16);
            cp16(d + 16384, Al + aoff, 16);
            int bn = bCol + row;
            int ok = (bn < N) ? 16 : 0;
            size_t boff = (size_t)(bn < N ? bn : 0) * ldb + kt + ch * 8;
            cp16(d + 32768, Bh + boff, ok);
            cp16(d + 49152, Bl + boff, ok);
        }
        CP_COMMIT();
    };

    loadStage(0);
    if (nChunks > 1) loadStage(1);
    for (int c = 0; c < nChunks; c++) {
        if (c + 2 < nChunks) { loadStage(c + 2); CP_WAIT(2); }
        else if (c + 1 < nChunks) { CP_WAIT(1); }
        else { CP_WAIT(0); }
        __syncthreads();
        const uint32_t st = sb + (c % NSTAGE) * STAGE_SZ;

        uint32_t baseA[4]; int r7A[4];
        #pragma unroll
        for (int mi = 0; mi < 4; mi++) {
            int r = wm + mi * 16 + (l & 15);
            baseA[mi] = st + r * 128;
            r7A[mi] = r & 7;
        }
        const int hkA = l >> 4;
        const int matb = l >> 3;
        const int rB0 = wn + (l & 7) + ((matb >> 1) << 3);
        const int hkB = matb & 1;

        #pragma unroll
        for (int ks = 0; ks < 4; ks++) {
            uint32_t Ahf[4][4], Alf[4][4], Bhf[4][2], Blf[4][2];
            #pragma unroll
            for (int mi = 0; mi < 4; mi++) {
                int ck = 2 * ks + hkA;
                uint32_t ad = baseA[mi] + ((ck ^ r7A[mi]) << 4);
                ldm_x4(Ahf[mi][0], Ahf[mi][1], Ahf[mi][2], Ahf[mi][3], ad);
                ldm_x4(Alf[mi][0], Alf[mi][1], Alf[mi][2], Alf[mi][3], ad + 16384);
            }
            #pragma unroll
            for (int ng = 0; ng < 2; ng++) {
                int r = rB0 + ng * 16;
                int ck = 2 * ks + hkB;
                uint32_t ad = st + 32768 + r * 128 + ((ck ^ (r & 7)) << 4);
                uint32_t t0, t1, t2, t3;
                ldm_x4(t0, t1, t2, t3, ad);
                Bhf[ng*2][0] = t0; Bhf[ng*2][1] = t1;
                Bhf[ng*2+1][0] = t2; Bhf[ng*2+1][1] = t3;
                ldm_x4(t0, t1, t2, t3, ad + 16384);
                Blf[ng*2][0] = t0; Blf[ng*2][1] = t1;
                Blf[ng*2+1][0] = t2; Blf[ng*2+1][1] = t3;
            }
            #pragma unroll
            for (int mi = 0; mi < 4; mi++)
                #pragma unroll
                for (int ni = 0; ni < 4; ni++) {
                    mma16816(acc[mi][ni], Ahf[mi], Bhf[ni]);
                    mma16816(acc[mi][ni], Ahf[mi], Blf[ni]);
                    mma16816(acc[mi][ni], Alf[mi], Bhf[ni]);
                }
        }
        __syncthreads();
    }

    if (TRANS) {
        // stage tile in smem (stages are dead now), then coalesced store
        float* ts = reinterpret_cast<float*>(smem);   // [128][132]
        #pragma unroll
        for (int mi = 0; mi < 4; mi++) {
            #pragma unroll
            for (int h2 = 0; h2 < 2; h2++) {
                int row = wm + mi * 16 + h2 * 8 + (l >> 2);
                #pragma unroll
                for (int ni = 0; ni < 4; ni++) {
                    int col = wn + ni * 8 + (l & 3) * 2;
                    float v0 = acc[mi][ni][h2 * 2 + 0];
                    float v1 = acc[mi][ni][h2 * 2 + 1];
                    if (EPI == 1) {
                        v0 = softplus_f(v0 + bias[bCol + col]);
                        v1 = softplus_f(v1 + bias[bCol + col + 1]);
                    }
                    ts[(col) * 132 + row] = v0;
                    ts[(col + 1) * 132 + row] = v1;
                }
            }
        }
        __syncthreads();
        #pragma unroll
        for (int i = 0; i < 64; i++) {
            int lin = i * 256 + tid;
            int r = lin >> 7, cc = lin & 127;
            C[(size_t)(bCol + r) * ldc + bRow + cc] = ts[r * 132 + cc];
        }
    } else {
        #pragma unroll
        for (int mi = 0; mi < 4; mi++) {
            #pragma unroll
            for (int h2 = 0; h2 < 2; h2++) {
                int row = bRow + wm + mi * 16 + h2 * 8 + (l >> 2);
                #pragma unroll
                for (int ni = 0; ni < 4; ni++) {
                    int col = bCol + wn + ni * 8 + (l & 3) * 2;
                    if (col < N) {
                        float v0 = acc[mi][ni][h2 * 2 + 0];
                        float v1 = acc[mi][ni][h2 * 2 + 1];
                        if (EPI == 1) {
                            v0 = softplus_f(v0 + bias[col]);
                            v1 = softplus_f(v1 + bias[col + 1]);
                        } else if (EPI == 2) {
                            const float* rr = res + (size_t)row * ldres + col;
                            v0 += rr[0]; v1 += rr[1];
                        }
                        *reinterpret_cast<float2*>(C + (size_t)row * ldc + col) =
                            make_float2(v0, v1);
                    }
                }
            }
        }
    }
}

// ---------------------------------------------------------------------------
// weight fp32 -> bf16 hi/lo
// ---------------------------------------------------------------------------
__global__ __launch_bounds__(256) void convert_w(
    const float* __restrict__ w, bf16* __restrict__ hi, bf16* __restrict__ lo,
    int n4)
{
    int i = blockIdx.x * 256 + threadIdx.x;
    if (i >= n4) return;
    float4 v = reinterpret_cast<const float4*>(w)[i];
    uint2 h, l;
    split4(v, h, l);
    reinterpret_cast<uint2*>(hi)[i] = h;
    reinterpret_cast<uint2*>(lo)[i] = l;
}

// ---------------------------------------------------------------------------
// RMSNorm -> bf16 hi/lo
// ---------------------------------------------------------------------------
__global__ __launch_bounds__(256) void rmsnorm_kernel(
    const float* __restrict__ x, const float* __restrict__ w,
    bf16* __restrict__ hh, bf16* __restrict__ hl)
{
    int row = blockIdx.x;
    int tid = threadIdx.x;
    float4 v = reinterpret_cast<const float4*>(x + (size_t)row * DMODEL)[tid];
    float ss = v.x * v.x + v.y * v.y + v.z * v.z + v.w * v.w;
    __shared__ float red[8];
    #pragma unroll
    for (int o = 16; o > 0; o >>= 1) ss += __shfl_xor_sync(0xffffffffu, ss, o);
    if ((tid & 31) == 0) red[tid >> 5] = ss;
    __syncthreads();
    if (tid < 32) {
        float t = (tid < 8) ? red[tid] : 0.f;
        #pragma unroll
        for (int o = 4; o > 0; o >>= 1) t += __shfl_xor_sync(0xffffffffu, t, o);
        if (tid == 0) red[0] = t;
    }
    __syncthreads();
    float scale = rsqrtf(red[0] * (1.0f / DMODEL) + 1e-5f);
    float4 wv = reinterpret_cast<const float4*>(w)[tid];
    float4 o;
    o.x = v.x * scale * wv.x;  o.y = v.y * scale * wv.y;
    o.z = v.z * scale * wv.z;  o.w = v.w * scale * wv.w;
    uint2 h, l;
    split4(o, h, l);
    reinterpret_cast<uint2*>(hh + (size_t)row * DMODEL)[tid] = h;
    reinterpret_cast<uint2*>(hl + (size_t)row * DMODEL)[tid] = l;
}

// ---------------------------------------------------------------------------
// Tiled conv(width4)+SiLU + silu(z). 32 tokens x 64 channels per block.
// All global reads/writes coalesced; transposed outputs staged through smem.
// ---------------------------------------------------------------------------
#define CT 32
#define CD 64

__global__ __launch_bounds__(256) void conv_silu_kernel(
    const float* __restrict__ xz,
    const float* __restrict__ conv_w, const float* __restrict__ conv_b,
    bf16* __restrict__ xsh, bf16* __restrict__ xsl,
    float* __restrict__ xsT, float* __restrict__ gT)
{
    __shared__ float xc[CT + 3][CD];
    __shared__ float sx[CD][CT + 1];
    __shared__ float sg[CD][CT + 1];

    const int tid = threadIdx.x;
    const int d0 = blockIdx.x * CD;
    const int t0 = blockIdx.y * CT;
    const bool halo = (t0 & (SEQ - 1)) != 0;   // halo rows valid within batch

    // load xc rows [t0-3, t0+31]
    #pragma unroll
    for (int it = 0; it < 9; it++) {
        int lin = it * 256 + tid;
        if (lin < (CT + 3) * CD) {
            int i = lin >> 6, ch = lin & 63;
            float v = 0.f;
            if (i >= 3 || halo)
                v = xz[(size_t)(t0 - 3 + i) * (2 * DINNER) + d0 + ch];
            xc[i][ch] = v;
        }
    }
    // gate tile
    #pragma unroll
    for (int it = 0; it < 8; it++) {
        int lin = it * 256 + tid;
        int tok = lin >> 6, ch = lin & 63;
        float zv = xz[(size_t)(t0 + tok) * (2 * DINNER) + DINNER + d0 + ch];
        sg[ch][tok] = silu_f(zv);
    }
    __syncthreads();

    // conv + silu; token-major bf16 out; stage transposed in smem
    #pragma unroll
    for (int it = 0; it < 8; it++) {
        int lin = it * 256 + tid;
        int tok = lin >> 6, ch = lin & 63;
        int d = d0 + ch;
        float a = conv_b[d];
        #pragma unroll
        for (int k = 0; k < DCONV; k++)
            a = fmaf(conv_w[d * DCONV + k], xc[tok + k][ch], a);
        float v = silu_f(a);
        sx[ch][tok] = v;
        bf16 h, l;
        split1(v, h, l);
        size_t o = (size_t)(t0 + tok) * DINNER + d;
        xsh[o] = h; xsl[o] = l;
    }
    __syncthreads();

    // coalesced transposed writes
    #pragma unroll
    for (int it = 0; it < 8; it++) {
        int lin = it * 256 + tid;
        int ch = lin >> 5, tok = lin & 31;
        size_t o = (size_t)(d0 + ch) * NTOK + t0 + tok;
        xsT[o] = sx[ch][tok];
        gT[o]  = sg[ch][tok];
    }
}

// ---------------------------------------------------------------------------
// split-K reduce for x_proj
// ---------------------------------------------------------------------------
__global__ __launch_bounds__(256) void reduce_xproj(
    const float* __restrict__ part,
    bf16* __restrict__ xdh, bf16* __restrict__ xdl,
    float* __restrict__ bcT)
{
    int idx = blockIdx.x * 256 + threadIdx.x;
    if (idx >= NTOK * XPROJ_N) return;
    float s = 0.f;
    #pragma unroll
    for (int z = 0; z < XSPLIT; z++) s += part[(size_t)z * NTOK * XPROJ_N + idx];
    bf16 h, l;
    split1(s, h, l);
    xdh[idx] = h; xdl[idx] = l;
    int row = idx / XPROJ_N, col = idx - row * XPROJ_N;
    if (col >= DTRANK)
        bcT[(size_t)(col - DTRANK) * NTOK + row] = s;
}

// ---------------------------------------------------------------------------
// selective scan + gate (transposed, float4 pipeline)
// ---------------------------------------------------------------------------
__global__ __launch_bounds__(256) void scan_kernel(
    const float* __restrict__ dtT, const float* __restrict__ xsT,
    const float* __restrict__ bcT, const float* __restrict__ gT,
    const float* __restrict__ A_log, const float* __restrict__ Dp,
    float* __restrict__ yT)
{
    int warp = threadIdx.x >> 5;
    int lane = threadIdx.x & 31;
    int chPair = blockIdx.x * 8 + warp;
    int ch = chPair * 2 + (lane >> 4);
    int b = ch >> 11;
    int d = ch & 2047;
    int n = lane & 15;
    int rowBase = b * SEQ;

    const float* dtp = dtT + (size_t)d * NTOK + rowBase;
    const float* xsp = xsT + (size_t)d * NTOK + rowBase;
    const float* gp  = gT  + (size_t)d * NTOK + rowBase;
    const float* Bp  = bcT + (size_t)n * NTOK + rowBase;
    const float* Cp  = bcT + (size_t)(DSTATE + n) * NTOK + rowBase;
    float* yp = yT + (size_t)d * NTOK + rowBase;

    float a  = -expf(A_log[d * DSTATE + n]);
    float Dv = Dp[d];
    float s = 0.f;

    float4 dt4 = *reinterpret_cast<const float4*>(dtp);
    float4 xs4 = *reinterpret_cast<const float4*>(xsp);
    float4 g4  = *reinterpret_cast<const float4*>(gp);
    float4 B4  = *reinterpret_cast<const float4*>(Bp);
    float4 C4  = *reinterpret_cast<const float4*>(Cp);

    for (int t = 0; t < SEQ; t += 4) {
        float4 ndt, nxs, ng, nB, nC;
        if (t + 4 < SEQ) {
            ndt = *reinterpret_cast<const float4*>(dtp + t + 4);
            nxs = *reinterpret_cast<const float4*>(xsp + t + 4);
            ng  = *reinterpret_cast<const float4*>(gp + t + 4);
            nB  = *reinterpret_cast<const float4*>(Bp + t + 4);
            nC  = *reinterpret_cast<const float4*>(Cp + t + 4);
        }
        const float* dtv = &dt4.x; const float* xsv = &xs4.x;
        const float* gv = &g4.x; const float* Bv = &B4.x; const float* Cv = &C4.x;
        float4 yout;
        float* yv = &yout.x;
        #pragma unroll
        for (int q = 0; q < 4; q++) {
            float dA = __expf(dtv[q] * a);
            s = fmaf(dA, s, dtv[q] * xsv[q] * Bv[q]);
            float p = s * Cv[q];
            p += __shfl_xor_sync(0xffffffffu, p, 8);
            p += __shfl_xor_sync(0xffffffffu, p, 4);
            p += __shfl_xor_sync(0xffffffffu, p, 2);
            p += __shfl_xor_sync(0xffffffffu, p, 1);
            yv[q] = (p + Dv * xsv[q]) * gv[q];
        }
        if (n == 0)
            *reinterpret_cast<float4*>(yp + t) = yout;
        dt4 = ndt; xs4 = nxs; g4 = ng; B4 = nB; C4 = nC;
    }
}

// ---------------------------------------------------------------------------
// yT fp32 -> y bf16 hi/lo (tiled transpose)
// ---------------------------------------------------------------------------
__global__ __launch_bounds__(256) void transpose_split(
    const float* __restrict__ yT, bf16* __restrict__ yh, bf16* __restrict__ yl)
{
    __shared__ float tile[32][33];
    int bx = blockIdx.x, by = blockIdx.y;
    int tx = threadIdx.x & 31, ty = threadIdx.x >> 5;
    #pragma unroll
    for (int j = 0; j < 32; j += 8) {
        int dd = by * 32 + ty + j;
        int tok = bx * 32 + tx;
        tile[ty + j][tx] = yT[(size_t)dd * NTOK + tok];
    }
    __syncthreads();
    #pragma unroll
    for (int j = 0; j < 32; j += 8) {
        int tok = bx * 32 + ty + j;
        int dd = by * 32 + tx;
        float v = tile[tx][ty + j];
        bf16 h, l;
        split1(v, h, l);
        yh[(size_t)tok * DINNER + dd] = h;
        yl[(size_t)tok * DINNER + dd] = l;
    }
}

// ---------------------------------------------------------------------------
// Launch
// ---------------------------------------------------------------------------
extern "C" void kernel_launch(void* const* d_in, const int* in_sizes, int n_in,
                              void* d_out, int out_size)
{
    const float* x         = (const float*)d_in[0];
    const float* norm_w    = (const float*)d_in[1];
    const float* in_proj_w = (const float*)d_in[2];
    const float* conv_w    = (const float*)d_in[3];
    const float* conv_b    = (const float*)d_in[4];
    const float* x_proj_w  = (const float*)d_in[5];
    const float* dt_proj_w = (const float*)d_in[6];
    const float* dt_proj_b = (const float*)d_in[7];
    const float* A_log     = (const float*)d_in[8];
    const float* Dp        = (const float*)d_in[9];
    const float* out_proj_w= (const float*)d_in[10];
    float* out = (float*)d_out;

    float *pxz, *pxsT, *pgT, *pdtT, *pbcT, *pyT, *ppart;
    bf16 *pwih, *pwil, *pwxh, *pwxl, *pwdh, *pwdl, *pwoh, *pwol;
    bf16 *phh, *phl, *pxsh, *pxsl, *pxdh, *pxdl, *pyh, *pyl;
    cudaGetSymbolAddress((void**)&pxz,  g_xz);
    cudaGetSymbolAddress((void**)&pxsT, g_xsT);
    cudaGetSymbolAddress((void**)&pgT,  g_gT);
    cudaGetSymbolAddress((void**)&pdtT, g_dtT);
    cudaGetSymbolAddress((void**)&pbcT, g_bcT);
    cudaGetSymbolAddress((void**)&pyT,  g_yT);
    cudaGetSymbolAddress((void**)&ppart,g_part);
    cudaGetSymbolAddress((void**)&pwih, g_wih); cudaGetSymbolAddress((void**)&pwil, g_wil);
    cudaGetSymbolAddress((void**)&pwxh, g_wxh); cudaGetSymbolAddress((void**)&pwxl, g_wxl);
    cudaGetSymbolAddress((void**)&pwdh, g_wdh); cudaGetSymbolAddress((void**)&pwdl, g_wdl);
    cudaGetSymbolAddress((void**)&pwoh, g_woh); cudaGetSymbolAddress((void**)&pwol, g_wol);
    cudaGetSymbolAddress((void**)&phh,  g_hh);  cudaGetSymbolAddress((void**)&phl,  g_hl);
    cudaGetSymbolAddress((void**)&pxsh, g_xsh); cudaGetSymbolAddress((void**)&pxsl, g_xsl);
    cudaGetSymbolAddress((void**)&pxdh, g_xdh); cudaGetSymbolAddress((void**)&pxdl, g_xdl);
    cudaGetSymbolAddress((void**)&pyh,  g_yh);  cudaGetSymbolAddress((void**)&pyl,  g_yl);

    cudaFuncSetAttribute(mma_gemm<0,0>, cudaFuncAttributeMaxDynamicSharedMemorySize, GEMM_SMEM);
    cudaFuncSetAttribute(mma_gemm<1,1>, cudaFuncAttributeMaxDynamicSharedMemorySize, GEMM_SMEM);
    cudaFuncSetAttribute(mma_gemm<2,0>, cudaFuncAttributeMaxDynamicSharedMemorySize, GEMM_SMEM);

    // 0) weight conversion
    convert_w<<<(2*DINNER*DMODEL/4 + 255)/256, 256>>>(in_proj_w,  pwih, pwil, 2*DINNER*DMODEL/4);
    convert_w<<<(XPROJ_N*DINNER/4 + 255)/256, 256>>>(x_proj_w,   pwxh, pwxl, XPROJ_N*DINNER/4);
    convert_w<<<(DINNER*DTRANK/4 + 255)/256, 256>>>(dt_proj_w,  pwdh, pwdl, DINNER*DTRANK/4);
    convert_w<<<(DMODEL*DINNER/4 + 255)/256, 256>>>(out_proj_w, pwoh, pwol, DMODEL*DINNER/4);

    // 1) RMSNorm
    rmsnorm_kernel<<<NTOK, 256>>>(x, norm_w, phh, phl);

    // 2) in_proj
    {
        dim3 grid((2 * DINNER) / 128, NTOK / 128, 1);
        mma_gemm<0,0><<<grid, 256, GEMM_SMEM>>>(
            phh, phl, DMODEL, pwih, pwil, DMODEL,
            pxz, 2 * DINNER, 2 * DINNER, DMODEL, 0, nullptr, nullptr, 0);
    }

    // 3) conv + silu (tiled, coalesced)
    {
        dim3 grid(DINNER / CD, NTOK / CT);
        conv_silu_kernel<<<grid, 256>>>(pxz, conv_w, conv_b,
                                        pxsh, pxsl, pxsT, pgT);
    }

    // 4) x_proj split-K
    {
        dim3 grid(1, NTOK / 128, XSPLIT);
        mma_gemm<0,0><<<grid, 256, GEMM_SMEM>>>(
            pxsh, pxsl, DINNER, pwxh, pwxl, DINNER,
            ppart, XPROJ_N, XPROJ_N, DINNER / XSPLIT,
            (long)NTOK * XPROJ_N, nullptr, nullptr, 0);
    }
    reduce_xproj<<<(NTOK * XPROJ_N + 255) / 256, 256>>>(ppart, pxdh, pxdl, pbcT);

    // 5) dt_proj + softplus (coalesced transposed store)
    {
        dim3 grid(DINNER / 128, NTOK / 128, 1);
        mma_gemm<1,1><<<grid, 256, GEMM_SMEM>>>(
            pxdh, pxdl, XPROJ_N, pwdh, pwdl, DTRANK,
            pdtT, NTOK, DINNER, DTRANK, 0, dt_proj_b, nullptr, 0);
    }

    // 6) scan -> yT
    scan_kernel<<<(BATCH * DINNER) / 16, 256>>>(pdtT, pxsT, pbcT, pgT,
                                                A_log, Dp, pyT);

    // 7) transpose + split y
    {
        dim3 grid(NTOK / 32, DINNER / 32);
        transpose_split<<<grid, 256>>>(pyT, pyh, pyl);
    }

    // 8) out_proj + residual
    {
        dim3 grid(DMODEL / 128, NTOK / 128, 1);
        mma_gemm<2,0><<<grid, 256, GEMM_SMEM>>>(
            pyh, pyl, DINNER, pwoh, pwol, DINNER,
            out, DMODEL, DMODEL, DINNER, 0, nullptr, x, DMODEL);
    }
}

// round 7
// speedup vs baseline: 1.9701x; 1.1000x over previous
#include <cuda_runtime.h>
#include <cuda_fp16.h>
#include <cstdint>
#include <math.h>

// ---------------------------------------------------------------------------
// Mamba block forward. GEMMs via mma.sync HMMA fp16 (activations hi+lo split,
// weights single fp16, fp32 accum, 2 MMA passes). Scan on transposed layout.
// ---------------------------------------------------------------------------

#define BATCH   2
#define SEQ     1024
#define DMODEL  1024
#define DINNER  2048
#define DSTATE  16
#define DTRANK  64
#define DCONV   4
#define NTOK    (BATCH * SEQ)
#define XPROJ_N (DTRANK + 2 * DSTATE)   // 96
#define XSPLIT  16

typedef __half f16;

// fp32 scratch
__device__ __align__(256) float g_xz[NTOK * 2 * DINNER];
__device__ __align__(256) float g_xsT[DINNER * NTOK];
__device__ __align__(256) float g_gT[DINNER * NTOK];
__device__ __align__(256) float g_dtT[DINNER * NTOK];
__device__ __align__(256) float g_bcT[2 * DSTATE * NTOK];
__device__ __align__(256) float g_yT[DINNER * NTOK];
__device__ __align__(256) float g_part[XSPLIT * NTOK * XPROJ_N];

// fp16 weights (single) + fp16 hi/lo activations
__device__ __align__(256) f16 g_wi[2 * DINNER * DMODEL];
__device__ __align__(256) f16 g_wx[XPROJ_N * DINNER];
__device__ __align__(256) f16 g_wd[DINNER * DTRANK];
__device__ __align__(256) f16 g_wo[DMODEL * DINNER];
__device__ __align__(256) f16 g_hh[NTOK * DMODEL],   g_hl[NTOK * DMODEL];
__device__ __align__(256) f16 g_xsh[NTOK * DINNER],  g_xsl[NTOK * DINNER];
__device__ __align__(256) f16 g_xdh[NTOK * XPROJ_N], g_xdl[NTOK * XPROJ_N];
__device__ __align__(256) f16 g_yh[NTOK * DINNER],   g_yl[NTOK * DINNER];

// ---------------------------------------------------------------------------
// helpers
// ---------------------------------------------------------------------------
__device__ __forceinline__ uint32_t smem_u32(const void* p) {
    uint32_t a;
    asm("{ .reg .u64 t; cvta.to.shared.u64 t, %1; cvt.u32.u64 %0, t; }"
        : "=r"(a) : "l"(p));
    return a;
}
__device__ __forceinline__ void ldm_x4(uint32_t& r0, uint32_t& r1,
                                       uint32_t& r2, uint32_t& r3, uint32_t a) {
    asm volatile("ldmatrix.sync.aligned.m8n8.x4.shared.b16 {%0,%1,%2,%3}, [%4];"
                 : "=r"(r0), "=r"(r1), "=r"(r2), "=r"(r3) : "r"(a));
}
__device__ __forceinline__ void mma16816(float* d, const uint32_t* a,
                                         const uint32_t* b) {
    asm volatile(
        "mma.sync.aligned.m16n8k16.row.col.f32.f16.f16.f32 "
        "{%0,%1,%2,%3}, {%4,%5,%6,%7}, {%8,%9}, {%0,%1,%2,%3};"
        : "+f"(d[0]), "+f"(d[1]), "+f"(d[2]), "+f"(d[3])
        : "r"(a[0]), "r"(a[1]), "r"(a[2]), "r"(a[3]), "r"(b[0]), "r"(b[1]));
}
__device__ __forceinline__ void cp16(uint32_t dst, const void* src, int sz) {
    asm volatile("cp.async.cg.shared.global [%0], [%1], 16, %2;"
                 :: "r"(dst), "l"(src), "r"(sz) : "memory");
}
#define CP_COMMIT() asm volatile("cp.async.commit_group;" ::: "memory")
#define CP_WAIT(n)  asm volatile("cp.async.wait_group %0;" :: "n"(n) : "memory")

__device__ __forceinline__ uint32_t pack2(f16 a, f16 b) {
    return ((uint32_t)__half_as_ushort(b) << 16) | __half_as_ushort(a);
}
__device__ __forceinline__ void split1(float v, f16& h, f16& l) {
    h = __float2half_rn(v);
    l = __float2half_rn(v - __half2float(h));
}
__device__ __forceinline__ void split4(float4 v, uint2& hi, uint2& lo) {
    f16 h0, l0, h1, l1, h2, l2, h3, l3;
    split1(v.x, h0, l0); split1(v.y, h1, l1);
    split1(v.z, h2, l2); split1(v.w, h3, l3);
    hi.x = pack2(h0, h1); hi.y = pack2(h2, h3);
    lo.x = pack2(l0, l1); lo.y = pack2(l2, l3);
}
__device__ __forceinline__ uint2 cvt4(float4 v) {
    uint2 r;
    r.x = pack2(__float2half_rn(v.x), __float2half_rn(v.y));
    r.y = pack2(__float2half_rn(v.z), __float2half_rn(v.w));
    return r;
}
__device__ __forceinline__ float softplus_f(float v) {
    return (v > 15.f) ? v : log1pf(__expf(v));
}
__device__ __forceinline__ float silu_f(float v) {
    return v / (1.f + __expf(-v));
}

// ---------------------------------------------------------------------------
// HMMA GEMM (NT): C[M,N] = A[M,K]·B[N,K]^T. A = hi+lo fp16, B = single fp16,
// fp32 accum, 2 MMA passes. CTA 128x128, 8 warps (64x32), K-chunk 64,
// 3-stage cp.async pipeline.
// EPI: 0 none, 1 softplus(acc+bias[n]), 2 acc+res[m,n].
// TRANS: 1 -> coalesced transposed store via smem staging.
// ---------------------------------------------------------------------------
#define STAGE_SZ 49152
#define NSTAGE 3
#define GEMM_SMEM (NSTAGE * STAGE_SZ)   // 144 KB

template<int EPI, int TRANS>
__global__ void __launch_bounds__(256, 1) mma_gemm(
    const f16* __restrict__ Ah, const f16* __restrict__ Al, int lda,
    const f16* __restrict__ B, int ldb,
    float* __restrict__ C, int ldc, int N, int Ksplit, long partStride,
    const float* __restrict__ bias, const float* __restrict__ res, int ldres)
{
    extern __shared__ char smem[];
    const uint32_t sb = smem_u32(smem);
    const int tid = threadIdx.x;
    const int bRow = blockIdx.y * 128, bCol = blockIdx.x * 128;
    const int kbase = blockIdx.z * Ksplit;
    C += (long)blockIdx.z * partStride;
    const int nChunks = Ksplit >> 6;

    const int wid = tid >> 5, l = tid & 31;
    const int wm = (wid >> 2) * 64, wn = (wid & 3) * 32;

    float acc[4][4][4];
    #pragma unroll
    for (int a = 0; a < 4; a++)
        #pragma unroll
        for (int b = 0; b < 4; b++)
            #pragma unroll
            for (int c = 0; c < 4; c++) acc[a][b][c] = 0.f;

    auto loadStage = [&](int c) {
        const int kt = kbase + (c << 6);
        const uint32_t base = sb + (c % NSTAGE) * STAGE_SZ;
        #pragma unroll
        for (int it = 0; it < 4; it++) {
            int lin = it * 256 + tid;
            int row = lin >> 3, ch = lin & 7;
            uint32_t d = base + row * 128 + (((ch ^ (row & 7)) << 4));
            size_t aoff = (size_t)(bRow + row) * lda + kt + ch * 8;
            cp16(d,         Ah + aoff, 16);
            cp16(d + 16384, Al + aoff, 16);
            int bn = bCol + row;
            int ok = (bn < N) ? 16 : 0;
            size_t boff = (size_t)(bn < N ? bn : 0) * ldb + kt + ch * 8;
            cp16(d + 32768, B + boff, ok);
        }
        CP_COMMIT();
    };

    loadStage(0);
    if (nChunks > 1) loadStage(1);
    for (int c = 0; c < nChunks; c++) {
        if (c + 2 < nChunks) { loadStage(c + 2); CP_WAIT(2); }
        else if (c + 1 < nChunks) { CP_WAIT(1); }
        else { CP_WAIT(0); }
        __syncthreads();
        const uint32_t st = sb + (c % NSTAGE) * STAGE_SZ;

        uint32_t baseA[4]; int r7A[4];
        #pragma unroll
        for (int mi = 0; mi < 4; mi++) {
            int r = wm + mi * 16 + (l & 15);
            baseA[mi] = st + r * 128;
            r7A[mi] = r & 7;
        }
        const int hkA = l >> 4;
        const int matb = l >> 3;
        const int rB0 = wn + (l & 7) + ((matb >> 1) << 3);
        const int hkB = matb & 1;

        #pragma unroll
        for (int ks = 0; ks < 4; ks++) {
            uint32_t Ahf[4][4], Alf[4][4], Bf[4][2];
            #pragma unroll
            for (int mi = 0; mi < 4; mi++) {
                int ck = 2 * ks + hkA;
                uint32_t ad = baseA[mi] + ((ck ^ r7A[mi]) << 4);
                ldm_x4(Ahf[mi][0], Ahf[mi][1], Ahf[mi][2], Ahf[mi][3], ad);
                ldm_x4(Alf[mi][0], Alf[mi][1], Alf[mi][2], Alf[mi][3], ad + 16384);
            }
            #pragma unroll
            for (int ng = 0; ng < 2; ng++) {
                int r = rB0 + ng * 16;
                int ck = 2 * ks + hkB;
                uint32_t ad = st + 32768 + r * 128 + ((ck ^ (r & 7)) << 4);
                uint32_t t0, t1, t2, t3;
                ldm_x4(t0, t1, t2, t3, ad);
                Bf[ng*2][0] = t0; Bf[ng*2][1] = t1;
                Bf[ng*2+1][0] = t2; Bf[ng*2+1][1] = t3;
            }
            #pragma unroll
            for (int mi = 0; mi < 4; mi++)
                #pragma unroll
                for (int ni = 0; ni < 4; ni++) {
                    mma16816(acc[mi][ni], Ahf[mi], Bf[ni]);
                    mma16816(acc[mi][ni], Alf[mi], Bf[ni]);
                }
        }
        __syncthreads();
    }

    if (TRANS) {
        float* ts = reinterpret_cast<float*>(smem);   // [128][132]
        #pragma unroll
        for (int mi = 0; mi < 4; mi++) {
            #pragma unroll
            for (int h2 = 0; h2 < 2; h2++) {
                int row = wm + mi * 16 + h2 * 8 + (l >> 2);
                #pragma unroll
                for (int ni = 0; ni < 4; ni++) {
                    int col = wn + ni * 8 + (l & 3) * 2;
                    float v0 = acc[mi][ni][h2 * 2 + 0];
                    float v1 = acc[mi][ni][h2 * 2 + 1];
                    if (EPI == 1) {
                        v0 = softplus_f(v0 + bias[bCol + col]);
                        v1 = softplus_f(v1 + bias[bCol + col + 1]);
                    }
                    ts[(col) * 132 + row] = v0;
                    ts[(col + 1) * 132 + row] = v1;
                }
            }
        }
        __syncthreads();
        #pragma unroll
        for (int i = 0; i < 64; i++) {
            int lin = i * 256 + tid;
            int r = lin >> 7, cc = lin & 127;
            C[(size_t)(bCol + r) * ldc + bRow + cc] = ts[r * 132 + cc];
        }
    } else {
        #pragma unroll
        for (int mi = 0; mi < 4; mi++) {
            #pragma unroll
            for (int h2 = 0; h2 < 2; h2++) {
                int row = bRow + wm + mi * 16 + h2 * 8 + (l >> 2);
                #pragma unroll
                for (int ni = 0; ni < 4; ni++) {
                    int col = bCol + wn + ni * 8 + (l & 3) * 2;
                    if (col < N) {
                        float v0 = acc[mi][ni][h2 * 2 + 0];
                        float v1 = acc[mi][ni][h2 * 2 + 1];
                        if (EPI == 1) {
                            v0 = softplus_f(v0 + bias[col]);
                            v1 = softplus_f(v1 + bias[col + 1]);
                        } else if (EPI == 2) {
                            const float* rr = res + (size_t)row * ldres + col;
                            v0 += rr[0]; v1 += rr[1];
                        }
                        *reinterpret_cast<float2*>(C + (size_t)row * ldc + col) =
                            make_float2(v0, v1);
                    }
                }
            }
        }
    }
}

// ---------------------------------------------------------------------------
// weight fp32 -> single fp16
// ---------------------------------------------------------------------------
__global__ __launch_bounds__(256) void convert_w(
    const float* __restrict__ w, f16* __restrict__ o, int n4)
{
    int i = blockIdx.x * 256 + threadIdx.x;
    if (i >= n4) return;
    float4 v = reinterpret_cast<const float4*>(w)[i];
    reinterpret_cast<uint2*>(o)[i] = cvt4(v);
}

// ---------------------------------------------------------------------------
// RMSNorm -> fp16 hi/lo
// ---------------------------------------------------------------------------
__global__ __launch_bounds__(256) void rmsnorm_kernel(
    const float* __restrict__ x, const float* __restrict__ w,
    f16* __restrict__ hh, f16* __restrict__ hl)
{
    int row = blockIdx.x;
    int tid = threadIdx.x;
    float4 v = reinterpret_cast<const float4*>(x + (size_t)row * DMODEL)[tid];
    float ss = v.x * v.x + v.y * v.y + v.z * v.z + v.w * v.w;
    __shared__ float red[8];
    #pragma unroll
    for (int o = 16; o > 0; o >>= 1) ss += __shfl_xor_sync(0xffffffffu, ss, o);
    if ((tid & 31) == 0) red[tid >> 5] = ss;
    __syncthreads();
    if (tid < 32) {
        float t = (tid < 8) ? red[tid] : 0.f;
        #pragma unroll
        for (int o = 4; o > 0; o >>= 1) t += __shfl_xor_sync(0xffffffffu, t, o);
        if (tid == 0) red[0] = t;
    }
    __syncthreads();
    float scale = rsqrtf(red[0] * (1.0f / DMODEL) + 1e-5f);
    float4 wv = reinterpret_cast<const float4*>(w)[tid];
    float4 o;
    o.x = v.x * scale * wv.x;  o.y = v.y * scale * wv.y;
    o.z = v.z * scale * wv.z;  o.w = v.w * scale * wv.w;
    uint2 h, l;
    split4(o, h, l);
    reinterpret_cast<uint2*>(hh + (size_t)row * DMODEL)[tid] = h;
    reinterpret_cast<uint2*>(hl + (size_t)row * DMODEL)[tid] = l;
}

// ---------------------------------------------------------------------------
// Tiled conv(width4)+SiLU + silu(z). 32 tok x 64 ch per block, coalesced.
// ---------------------------------------------------------------------------
#define CT 32
#define CD 64

__global__ __launch_bounds__(256) void conv_silu_kernel(
    const float* __restrict__ xz,
    const float* __restrict__ conv_w, const float* __restrict__ conv_b,
    f16* __restrict__ xsh, f16* __restrict__ xsl,
    float* __restrict__ xsT, float* __restrict__ gT)
{
    __shared__ float xc[CT + 3][CD];
    __shared__ float sx[CD][CT + 1];
    __shared__ float sg[CD][CT + 1];

    const int tid = threadIdx.x;
    const int d0 = blockIdx.x * CD;
    const int t0 = blockIdx.y * CT;
    const bool halo = (t0 & (SEQ - 1)) != 0;

    #pragma unroll
    for (int it = 0; it < 9; it++) {
        int lin = it * 256 + tid;
        if (lin < (CT + 3) * CD) {
            int i = lin >> 6, ch = lin & 63;
            float v = 0.f;
            if (i >= 3 || halo)
                v = xz[(size_t)(t0 - 3 + i) * (2 * DINNER) + d0 + ch];
            xc[i][ch] = v;
        }
    }
    #pragma unroll
    for (int it = 0; it < 8; it++) {
        int lin = it * 256 + tid;
        int tok = lin >> 6, ch = lin & 63;
        float zv = xz[(size_t)(t0 + tok) * (2 * DINNER) + DINNER + d0 + ch];
        sg[ch][tok] = silu_f(zv);
    }
    __syncthreads();

    #pragma unroll
    for (int it = 0; it < 8; it++) {
        int lin = it * 256 + tid;
        int tok = lin >> 6, ch = lin & 63;
        int d = d0 + ch;
        float a = conv_b[d];
        #pragma unroll
        for (int k = 0; k < DCONV; k++)
            a = fmaf(conv_w[d * DCONV + k], xc[tok + k][ch], a);
        float v = silu_f(a);
        sx[ch][tok] = v;
        f16 h, l;
        split1(v, h, l);
        size_t o = (size_t)(t0 + tok) * DINNER + d;
        xsh[o] = h; xsl[o] = l;
    }
    __syncthreads();

    #pragma unroll
    for (int it = 0; it < 8; it++) {
        int lin = it * 256 + tid;
        int ch = lin >> 5, tok = lin & 31;
        size_t o = (size_t)(d0 + ch) * NTOK + t0 + tok;
        xsT[o] = sx[ch][tok];
        gT[o]  = sg[ch][tok];
    }
}

// ---------------------------------------------------------------------------
// split-K reduce for x_proj
// ---------------------------------------------------------------------------
__global__ __launch_bounds__(256) void reduce_xproj(
    const float* __restrict__ part,
    f16* __restrict__ xdh, f16* __restrict__ xdl,
    float* __restrict__ bcT)
{
    int idx = blockIdx.x * 256 + threadIdx.x;
    if (idx >= NTOK * XPROJ_N) return;
    float s = 0.f;
    #pragma unroll
    for (int z = 0; z < XSPLIT; z++) s += part[(size_t)z * NTOK * XPROJ_N + idx];
    f16 h, l;
    split1(s, h, l);
    xdh[idx] = h; xdl[idx] = l;
    int row = idx / XPROJ_N, col = idx - row * XPROJ_N;
    if (col >= DTRANK)
        bcT[(size_t)(col - DTRANK) * NTOK + row] = s;
}

// ---------------------------------------------------------------------------
// selective scan + gate (transposed, float4 pipeline)
// ---------------------------------------------------------------------------
__global__ __launch_bounds__(256) void scan_kernel(
    const float* __restrict__ dtT, const float* __restrict__ xsT,
    const float* __restrict__ bcT, const float* __restrict__ gT,
    const float* __restrict__ A_log, const float* __restrict__ Dp,
    float* __restrict__ yT)
{
    int warp = threadIdx.x >> 5;
    int lane = threadIdx.x & 31;
    int chPair = blockIdx.x * 8 + warp;
    int ch = chPair * 2 + (lane >> 4);
    int b = ch >> 11;
    int d = ch & 2047;
    int n = lane & 15;
    int rowBase = b * SEQ;

    const float* dtp = dtT + (size_t)d * NTOK + rowBase;
    const float* xsp = xsT + (size_t)d * NTOK + rowBase;
    const float* gp  = gT  + (size_t)d * NTOK + rowBase;
    const float* Bp  = bcT + (size_t)n * NTOK + rowBase;
    const float* Cp  = bcT + (size_t)(DSTATE + n) * NTOK + rowBase;
    float* yp = yT + (size_t)d * NTOK + rowBase;

    float a  = -expf(A_log[d * DSTATE + n]);
    float Dv = Dp[d];
    float s = 0.f;

    float4 dt4 = *reinterpret_cast<const float4*>(dtp);
    float4 xs4 = *reinterpret_cast<const float4*>(xsp);
    float4 g4  = *reinterpret_cast<const float4*>(gp);
    float4 B4  = *reinterpret_cast<const float4*>(Bp);
    float4 C4  = *reinterpret_cast<const float4*>(Cp);

    for (int t = 0; t < SEQ; t += 4) {
        float4 ndt, nxs, ng, nB, nC;
        if (t + 4 < SEQ) {
            ndt = *reinterpret_cast<const float4*>(dtp + t + 4);
            nxs = *reinterpret_cast<const float4*>(xsp + t + 4);
            ng  = *reinterpret_cast<const float4*>(gp + t + 4);
            nB  = *reinterpret_cast<const float4*>(Bp + t + 4);
            nC  = *reinterpret_cast<const float4*>(Cp + t + 4);
        }
        const float* dtv = &dt4.x; const float* xsv = &xs4.x;
        const float* gv = &g4.x; const float* Bv = &B4.x; const float* Cv = &C4.x;
        float4 yout;
        float* yv = &yout.x;
        #pragma unroll
        for (int q = 0; q < 4; q++) {
            float dA = __expf(dtv[q] * a);
            s = fmaf(dA, s, dtv[q] * xsv[q] * Bv[q]);
            float p = s * Cv[q];
            p += __shfl_xor_sync(0xffffffffu, p, 8);
            p += __shfl_xor_sync(0xffffffffu, p, 4);
            p += __shfl_xor_sync(0xffffffffu, p, 2);
            p += __shfl_xor_sync(0xffffffffu, p, 1);
            yv[q] = (p + Dv * xsv[q]) * gv[q];
        }
        if (n == 0)
            *reinterpret_cast<float4*>(yp + t) = yout;
        dt4 = ndt; xs4 = nxs; g4 = ng; B4 = nB; C4 = nC;
    }
}

// ---------------------------------------------------------------------------
// yT fp32 -> y fp16 hi/lo (tiled transpose)
// ---------------------------------------------------------------------------
__global__ __launch_bounds__(256) void transpose_split(
    const float* __restrict__ yT, f16* __restrict__ yh, f16* __restrict__ yl)
{
    __shared__ float tile[32][33];
    int bx = blockIdx.x, by = blockIdx.y;
    int tx = threadIdx.x & 31, ty = threadIdx.x >> 5;
    #pragma unroll
    for (int j = 0; j < 32; j += 8) {
        int dd = by * 32 + ty + j;
        int tok = bx * 32 + tx;
        tile[ty + j][tx] = yT[(size_t)dd * NTOK + tok];
    }
    __syncthreads();
    #pragma unroll
    for (int j = 0; j < 32; j += 8) {
        int tok = bx * 32 + ty + j;
        int dd = by * 32 + tx;
        float v = tile[tx][ty + j];
        f16 h, l;
        split1(v, h, l);
        yh[(size_t)tok * DINNER + dd] = h;
        yl[(size_t)tok * DINNER + dd] = l;
    }
}

// ---------------------------------------------------------------------------
// Launch
// ---------------------------------------------------------------------------
extern "C" void kernel_launch(void* const* d_in, const int* in_sizes, int n_in,
                              void* d_out, int out_size)
{
    const float* x         = (const float*)d_in[0];
    const float* norm_w    = (const float*)d_in[1];
    const float* in_proj_w = (const float*)d_in[2];
    const float* conv_w    = (const float*)d_in[3];
    const float* conv_b    = (const float*)d_in[4];
    const float* x_proj_w  = (const float*)d_in[5];
    const float* dt_proj_w = (const float*)d_in[6];
    const float* dt_proj_b = (const float*)d_in[7];
    const float* A_log     = (const float*)d_in[8];
    const float* Dp        = (const float*)d_in[9];
    const float* out_proj_w= (const float*)d_in[10];
    float* out = (float*)d_out;

    float *pxz, *pxsT, *pgT, *pdtT, *pbcT, *pyT, *ppart;
    f16 *pwi, *pwx, *pwd, *pwo;
    f16 *phh, *phl, *pxsh, *pxsl, *pxdh, *pxdl, *pyh, *pyl;
    cudaGetSymbolAddress((void**)&pxz,  g_xz);
    cudaGetSymbolAddress((void**)&pxsT, g_xsT);
    cudaGetSymbolAddress((void**)&pgT,  g_gT);
    cudaGetSymbolAddress((void**)&pdtT, g_dtT);
    cudaGetSymbolAddress((void**)&pbcT, g_bcT);
    cudaGetSymbolAddress((void**)&pyT,  g_yT);
    cudaGetSymbolAddress((void**)&ppart,g_part);
    cudaGetSymbolAddress((void**)&pwi,  g_wi);
    cudaGetSymbolAddress((void**)&pwx,  g_wx);
    cudaGetSymbolAddress((void**)&pwd,  g_wd);
    cudaGetSymbolAddress((void**)&pwo,  g_wo);
    cudaGetSymbolAddress((void**)&phh,  g_hh);  cudaGetSymbolAddress((void**)&phl,  g_hl);
    cudaGetSymbolAddress((void**)&pxsh, g_xsh); cudaGetSymbolAddress((void**)&pxsl, g_xsl);
    cudaGetSymbolAddress((void**)&pxdh, g_xdh); cudaGetSymbolAddress((void**)&pxdl, g_xdl);
    cudaGetSymbolAddress((void**)&pyh,  g_yh);  cudaGetSymbolAddress((void**)&pyl,  g_yl);

    cudaFuncSetAttribute(mma_gemm<0,0>, cudaFuncAttributeMaxDynamicSharedMemorySize, GEMM_SMEM);
    cudaFuncSetAttribute(mma_gemm<1,1>, cudaFuncAttributeMaxDynamicSharedMemorySize, GEMM_SMEM);
    cudaFuncSetAttribute(mma_gemm<2,0>, cudaFuncAttributeMaxDynamicSharedMemorySize, GEMM_SMEM);

    // 0) weight conversion (fp32 -> fp16)
    convert_w<<<(2*DINNER*DMODEL/4 + 255)/256, 256>>>(in_proj_w,  pwi, 2*DINNER*DMODEL/4);
    convert_w<<<(XPROJ_N*DINNER/4 + 255)/256, 256>>>(x_proj_w,   pwx, XPROJ_N*DINNER/4);
    convert_w<<<(DINNER*DTRANK/4 + 255)/256, 256>>>(dt_proj_w,  pwd, DINNER*DTRANK/4);
    convert_w<<<(DMODEL*DINNER/4 + 255)/256, 256>>>(out_proj_w, pwo, DMODEL*DINNER/4);

    // 1) RMSNorm
    rmsnorm_kernel<<<NTOK, 256>>>(x, norm_w, phh, phl);

    // 2) in_proj
    {
        dim3 grid((2 * DINNER) / 128, NTOK / 128, 1);
        mma_gemm<0,0><<<grid, 256, GEMM_SMEM>>>(
            phh, phl, DMODEL, pwi, DMODEL,
            pxz, 2 * DINNER, 2 * DINNER, DMODEL, 0, nullptr, nullptr, 0);
    }

    // 3) conv + silu (tiled, coalesced)
    {
        dim3 grid(DINNER / CD, NTOK / CT);
        conv_silu_kernel<<<grid, 256>>>(pxz, conv_w, conv_b,
                                        pxsh, pxsl, pxsT, pgT);
    }

    // 4) x_proj split-K
    {
        dim3 grid(1, NTOK / 128, XSPLIT);
        mma_gemm<0,0><<<grid, 256, GEMM_SMEM>>>(
            pxsh, pxsl, DINNER, pwx, DINNER,
            ppart, XPROJ_N, XPROJ_N, DINNER / XSPLIT,
            (long)NTOK * XPROJ_N, nullptr, nullptr, 0);
    }
    reduce_xproj<<<(NTOK * XPROJ_N + 255) / 256, 256>>>(ppart, pxdh, pxdl, pbcT);

    // 5) dt_proj + softplus (coalesced transposed store)
    {
        dim3 grid(DINNER / 128, NTOK / 128, 1);
        mma_gemm<1,1><<<grid, 256, GEMM_SMEM>>>(
            pxdh, pxdl, XPROJ_N, pwd, DTRANK,
            pdtT, NTOK, DINNER, DTRANK, 0, dt_proj_b, nullptr, 0);
    }

    // 6) scan -> yT
    scan_kernel<<<(BATCH * DINNER) / 16, 256>>>(pdtT, pxsT, pbcT, pgT,
                                                A_log, Dp, pyT);

    // 7) transpose + split y
    {
        dim3 grid(NTOK / 32, DINNER / 32);
        transpose_split<<<grid, 256>>>(pyT, pyh, pyl);
    }

    // 8) out_proj + residual
    {
        dim3 grid(DMODEL / 128, NTOK / 128, 1);
        mma_gemm<2,0><<<grid, 256, GEMM_SMEM>>>(
            pyh, pyl, DINNER, pwo, DINNER,
            out, DMODEL, DMODEL, DINNER, 0, nullptr, x, DMODEL);
    }
}

// round 8
// speedup vs baseline: 2.4750x; 1.2563x over previous
#include <cuda_runtime.h>
#include <cuda_fp16.h>
#include <cstdint>
#include <math.h>

// ---------------------------------------------------------------------------
// Mamba block forward. GEMMs via mma.sync HMMA fp16 single-pass (fp32 accum).
// 128x128 CTA tiles, 3-stage cp.async, 2 CTAs/SM. Scan on transposed layout.
// ---------------------------------------------------------------------------

#define BATCH   2
#define SEQ     1024
#define DMODEL  1024
#define DINNER  2048
#define DSTATE  16
#define DTRANK  64
#define DCONV   4
#define NTOK    (BATCH * SEQ)
#define XPROJ_N (DTRANK + 2 * DSTATE)   // 96
#define XSPLIT  16

typedef __half f16;

// fp32 scratch
__device__ __align__(256) float g_xz[NTOK * 2 * DINNER];
__device__ __align__(256) float g_xsT[DINNER * NTOK];
__device__ __align__(256) float g_gT[DINNER * NTOK];
__device__ __align__(256) float g_dtT[DINNER * NTOK];
__device__ __align__(256) float g_bcT[2 * DSTATE * NTOK];
__device__ __align__(256) float g_yT[DINNER * NTOK];
__device__ __align__(256) float g_part[XSPLIT * NTOK * XPROJ_N];

// fp16 weights + activations (single precision fp16)
__device__ __align__(256) f16 g_wi[2 * DINNER * DMODEL];
__device__ __align__(256) f16 g_wx[XPROJ_N * DINNER];
__device__ __align__(256) f16 g_wd[DINNER * DTRANK];
__device__ __align__(256) f16 g_wo[DMODEL * DINNER];
__device__ __align__(256) f16 g_hh[NTOK * DMODEL];
__device__ __align__(256) f16 g_xsh[NTOK * DINNER];
__device__ __align__(256) f16 g_xdh[NTOK * XPROJ_N];
__device__ __align__(256) f16 g_yh[NTOK * DINNER];

// ---------------------------------------------------------------------------
// helpers
// ---------------------------------------------------------------------------
__device__ __forceinline__ uint32_t smem_u32(const void* p) {
    uint32_t a;
    asm("{ .reg .u64 t; cvta.to.shared.u64 t, %1; cvt.u32.u64 %0, t; }"
        : "=r"(a) : "l"(p));
    return a;
}
__device__ __forceinline__ void ldm_x4(uint32_t& r0, uint32_t& r1,
                                       uint32_t& r2, uint32_t& r3, uint32_t a) {
    asm volatile("ldmatrix.sync.aligned.m8n8.x4.shared.b16 {%0,%1,%2,%3}, [%4];"
                 : "=r"(r0), "=r"(r1), "=r"(r2), "=r"(r3) : "r"(a));
}
__device__ __forceinline__ void mma16816(float* d, const uint32_t* a,
                                         const uint32_t* b) {
    asm volatile(
        "mma.sync.aligned.m16n8k16.row.col.f32.f16.f16.f32 "
        "{%0,%1,%2,%3}, {%4,%5,%6,%7}, {%8,%9}, {%0,%1,%2,%3};"
        : "+f"(d[0]), "+f"(d[1]), "+f"(d[2]), "+f"(d[3])
        : "r"(a[0]), "r"(a[1]), "r"(a[2]), "r"(a[3]), "r"(b[0]), "r"(b[1]));
}
__device__ __forceinline__ void cp16(uint32_t dst, const void* src, int sz) {
    asm volatile("cp.async.cg.shared.global [%0], [%1], 16, %2;"
                 :: "r"(dst), "l"(src), "r"(sz) : "memory");
}
#define CP_COMMIT() asm volatile("cp.async.commit_group;" ::: "memory")
#define CP_WAIT(n)  asm volatile("cp.async.wait_group %0;" :: "n"(n) : "memory")

__device__ __forceinline__ uint32_t pack2(f16 a, f16 b) {
    return ((uint32_t)__half_as_ushort(b) << 16) | __half_as_ushort(a);
}
__device__ __forceinline__ uint2 cvt4(float4 v) {
    uint2 r;
    r.x = pack2(__float2half_rn(v.x), __float2half_rn(v.y));
    r.y = pack2(__float2half_rn(v.z), __float2half_rn(v.w));
    return r;
}
__device__ __forceinline__ float softplus_f(float v) {
    return (v > 15.f) ? v : log1pf(__expf(v));
}
__device__ __forceinline__ float silu_f(float v) {
    return v / (1.f + __expf(-v));
}

// ---------------------------------------------------------------------------
// HMMA GEMM (NT): C[M,N] = A[M,K]·B[N,K]^T, fp16 x fp16 -> fp32.
// CTA 128x128, 8 warps (64x32), K-chunk 64, 3-stage cp.async, 2 CTAs/SM.
// EPI: 0 none, 1 softplus(acc+bias[n]), 2 acc+res[m,n].
// TRANS: 1 -> coalesced transposed store via smem staging.
// ---------------------------------------------------------------------------
#define STAGE_SZ 32768
#define NSTAGE 3
#define GEMM_SMEM (NSTAGE * STAGE_SZ)   // 96 KB

template<int EPI, int TRANS>
__global__ void __launch_bounds__(256, 2) mma_gemm(
    const f16* __restrict__ A, int lda,
    const f16* __restrict__ B, int ldb,
    float* __restrict__ C, int ldc, int N, int Ksplit, long partStride,
    const float* __restrict__ bias, const float* __restrict__ res, int ldres)
{
    extern __shared__ char smem[];
    const uint32_t sb = smem_u32(smem);
    const int tid = threadIdx.x;
    const int bRow = blockIdx.y * 128, bCol = blockIdx.x * 128;
    const int kbase = blockIdx.z * Ksplit;
    C += (long)blockIdx.z * partStride;
    const int nChunks = Ksplit >> 6;

    const int wid = tid >> 5, l = tid & 31;
    const int wm = (wid >> 2) * 64, wn = (wid & 3) * 32;

    float acc[4][4][4];
    #pragma unroll
    for (int a = 0; a < 4; a++)
        #pragma unroll
        for (int b = 0; b < 4; b++)
            #pragma unroll
            for (int c = 0; c < 4; c++) acc[a][b][c] = 0.f;

    auto loadStage = [&](int c) {
        const int kt = kbase + (c << 6);
        const uint32_t base = sb + (c % NSTAGE) * STAGE_SZ;
        #pragma unroll
        for (int it = 0; it < 4; it++) {
            int lin = it * 256 + tid;
            int row = lin >> 3, ch = lin & 7;
            uint32_t d = base + row * 128 + (((ch ^ (row & 7)) << 4));
            size_t aoff = (size_t)(bRow + row) * lda + kt + ch * 8;
            cp16(d, A + aoff, 16);
            int bn = bCol + row;
            int ok = (bn < N) ? 16 : 0;
            size_t boff = (size_t)(bn < N ? bn : 0) * ldb + kt + ch * 8;
            cp16(d + 16384, B + boff, ok);
        }
        CP_COMMIT();
    };

    loadStage(0);
    if (nChunks > 1) loadStage(1);
    for (int c = 0; c < nChunks; c++) {
        if (c + 2 < nChunks) { loadStage(c + 2); CP_WAIT(2); }
        else if (c + 1 < nChunks) { CP_WAIT(1); }
        else { CP_WAIT(0); }
        __syncthreads();
        const uint32_t st = sb + (c % NSTAGE) * STAGE_SZ;

        const int hkA = l >> 4;
        const int matb = l >> 3;
        const int rB0 = wn + (l & 7) + ((matb >> 1) << 3);
        const int hkB = matb & 1;

        #pragma unroll
        for (int ks = 0; ks < 4; ks++) {
            uint32_t Af[4][4], Bf[4][2];
            #pragma unroll
            for (int mi = 0; mi < 4; mi++) {
                int r = wm + mi * 16 + (l & 15);
                int ck = 2 * ks + hkA;
                uint32_t ad = st + r * 128 + ((ck ^ (r & 7)) << 4);
                ldm_x4(Af[mi][0], Af[mi][1], Af[mi][2], Af[mi][3], ad);
            }
            #pragma unroll
            for (int ng = 0; ng < 2; ng++) {
                int r = rB0 + ng * 16;
                int ck = 2 * ks + hkB;
                uint32_t ad = st + 16384 + r * 128 + ((ck ^ (r & 7)) << 4);
                uint32_t t0, t1, t2, t3;
                ldm_x4(t0, t1, t2, t3, ad);
                Bf[ng*2][0] = t0; Bf[ng*2][1] = t1;
                Bf[ng*2+1][0] = t2; Bf[ng*2+1][1] = t3;
            }
            #pragma unroll
            for (int mi = 0; mi < 4; mi++)
                #pragma unroll
                for (int ni = 0; ni < 4; ni++)
                    mma16816(acc[mi][ni], Af[mi], Bf[ni]);
        }
        __syncthreads();
    }

    if (TRANS) {
        // stage tile in smem (only 96KB; use [128][132] floats = 67584B OK)
        float* ts = reinterpret_cast<float*>(smem);
        #pragma unroll
        for (int mi = 0; mi < 4; mi++) {
            #pragma unroll
            for (int h2 = 0; h2 < 2; h2++) {
                int row = wm + mi * 16 + h2 * 8 + (l >> 2);
                #pragma unroll
                for (int ni = 0; ni < 4; ni++) {
                    int col = wn + ni * 8 + (l & 3) * 2;
                    float v0 = acc[mi][ni][h2 * 2 + 0];
                    float v1 = acc[mi][ni][h2 * 2 + 1];
                    if (EPI == 1) {
                        v0 = softplus_f(v0 + bias[bCol + col]);
                        v1 = softplus_f(v1 + bias[bCol + col + 1]);
                    }
                    ts[(col) * 132 + row] = v0;
                    ts[(col + 1) * 132 + row] = v1;
                }
            }
        }
        __syncthreads();
        #pragma unroll
        for (int i = 0; i < 64; i++) {
            int lin = i * 256 + tid;
            int r = lin >> 7, cc = lin & 127;
            C[(size_t)(bCol + r) * ldc + bRow + cc] = ts[r * 132 + cc];
        }
    } else {
        #pragma unroll
        for (int mi = 0; mi < 4; mi++) {
            #pragma unroll
            for (int h2 = 0; h2 < 2; h2++) {
                int row = bRow + wm + mi * 16 + h2 * 8 + (l >> 2);
                #pragma unroll
                for (int ni = 0; ni < 4; ni++) {
                    int col = bCol + wn + ni * 8 + (l & 3) * 2;
                    if (col < N) {
                        float v0 = acc[mi][ni][h2 * 2 + 0];
                        float v1 = acc[mi][ni][h2 * 2 + 1];
                        if (EPI == 1) {
                            v0 = softplus_f(v0 + bias[col]);
                            v1 = softplus_f(v1 + bias[col + 1]);
                        } else if (EPI == 2) {
                            const float* rr = res + (size_t)row * ldres + col;
                            v0 += rr[0]; v1 += rr[1];
                        }
                        *reinterpret_cast<float2*>(C + (size_t)row * ldc + col) =
                            make_float2(v0, v1);
                    }
                }
            }
        }
    }
}

// ---------------------------------------------------------------------------
// weight fp32 -> fp16
// ---------------------------------------------------------------------------
__global__ __launch_bounds__(256) void convert_w(
    const float* __restrict__ w, f16* __restrict__ o, int n4)
{
    int i = blockIdx.x * 256 + threadIdx.x;
    if (i >= n4) return;
    float4 v = reinterpret_cast<const float4*>(w)[i];
    reinterpret_cast<uint2*>(o)[i] = cvt4(v);
}

// ---------------------------------------------------------------------------
// RMSNorm -> fp16
// ---------------------------------------------------------------------------
__global__ __launch_bounds__(256) void rmsnorm_kernel(
    const float* __restrict__ x, const float* __restrict__ w,
    f16* __restrict__ hh)
{
    int row = blockIdx.x;
    int tid = threadIdx.x;
    float4 v = reinterpret_cast<const float4*>(x + (size_t)row * DMODEL)[tid];
    float ss = v.x * v.x + v.y * v.y + v.z * v.z + v.w * v.w;
    __shared__ float red[8];
    #pragma unroll
    for (int o = 16; o > 0; o >>= 1) ss += __shfl_xor_sync(0xffffffffu, ss, o);
    if ((tid & 31) == 0) red[tid >> 5] = ss;
    __syncthreads();
    if (tid < 32) {
        float t = (tid < 8) ? red[tid] : 0.f;
        #pragma unroll
        for (int o = 4; o > 0; o >>= 1) t += __shfl_xor_sync(0xffffffffu, t, o);
        if (tid == 0) red[0] = t;
    }
    __syncthreads();
    float scale = rsqrtf(red[0] * (1.0f / DMODEL) + 1e-5f);
    float4 wv = reinterpret_cast<const float4*>(w)[tid];
    float4 o;
    o.x = v.x * scale * wv.x;  o.y = v.y * scale * wv.y;
    o.z = v.z * scale * wv.z;  o.w = v.w * scale * wv.w;
    reinterpret_cast<uint2*>(hh + (size_t)row * DMODEL)[tid] = cvt4(o);
}

// ---------------------------------------------------------------------------
// Tiled conv(width4)+SiLU + silu(z). 32 tok x 64 ch per block, coalesced.
// ---------------------------------------------------------------------------
#define CT 32
#define CD 64

__global__ __launch_bounds__(256) void conv_silu_kernel(
    const float* __restrict__ xz,
    const float* __restrict__ conv_w, const float* __restrict__ conv_b,
    f16* __restrict__ xsh,
    float* __restrict__ xsT, float* __restrict__ gT)
{
    __shared__ float xc[CT + 3][CD];
    __shared__ float sx[CD][CT + 1];
    __shared__ float sg[CD][CT + 1];

    const int tid = threadIdx.x;
    const int d0 = blockIdx.x * CD;
    const int t0 = blockIdx.y * CT;
    const bool halo = (t0 & (SEQ - 1)) != 0;

    #pragma unroll
    for (int it = 0; it < 9; it++) {
        int lin = it * 256 + tid;
        if (lin < (CT + 3) * CD) {
            int i = lin >> 6, ch = lin & 63;
            float v = 0.f;
            if (i >= 3 || halo)
                v = xz[(size_t)(t0 - 3 + i) * (2 * DINNER) + d0 + ch];
            xc[i][ch] = v;
        }
    }
    #pragma unroll
    for (int it = 0; it < 8; it++) {
        int lin = it * 256 + tid;
        int tok = lin >> 6, ch = lin & 63;
        float zv = xz[(size_t)(t0 + tok) * (2 * DINNER) + DINNER + d0 + ch];
        sg[ch][tok] = silu_f(zv);
    }
    __syncthreads();

    #pragma unroll
    for (int it = 0; it < 8; it++) {
        int lin = it * 256 + tid;
        int tok = lin >> 6, ch = lin & 63;
        int d = d0 + ch;
        float a = conv_b[d];
        #pragma unroll
        for (int k = 0; k < DCONV; k++)
            a = fmaf(conv_w[d * DCONV + k], xc[tok + k][ch], a);
        float v = silu_f(a);
        sx[ch][tok] = v;
        xsh[(size_t)(t0 + tok) * DINNER + d] = __float2half_rn(v);
    }
    __syncthreads();

    #pragma unroll
    for (int it = 0; it < 8; it++) {
        int lin = it * 256 + tid;
        int ch = lin >> 5, tok = lin & 31;
        size_t o = (size_t)(d0 + ch) * NTOK + t0 + tok;
        xsT[o] = sx[ch][tok];
        gT[o]  = sg[ch][tok];
    }
}

// ---------------------------------------------------------------------------
// split-K reduce for x_proj
// ---------------------------------------------------------------------------
__global__ __launch_bounds__(256) void reduce_xproj(
    const float* __restrict__ part,
    f16* __restrict__ xdh,
    float* __restrict__ bcT)
{
    int idx = blockIdx.x * 256 + threadIdx.x;
    if (idx >= NTOK * XPROJ_N) return;
    float s = 0.f;
    #pragma unroll
    for (int z = 0; z < XSPLIT; z++) s += part[(size_t)z * NTOK * XPROJ_N + idx];
    xdh[idx] = __float2half_rn(s);
    int row = idx / XPROJ_N, col = idx - row * XPROJ_N;
    if (col >= DTRANK)
        bcT[(size_t)(col - DTRANK) * NTOK + row] = s;
}

// ---------------------------------------------------------------------------
// selective scan + gate (transposed, float4 pipeline)
// ---------------------------------------------------------------------------
__global__ __launch_bounds__(256) void scan_kernel(
    const float* __restrict__ dtT, const float* __restrict__ xsT,
    const float* __restrict__ bcT, const float* __restrict__ gT,
    const float* __restrict__ A_log, const float* __restrict__ Dp,
    float* __restrict__ yT)
{
    int warp = threadIdx.x >> 5;
    int lane = threadIdx.x & 31;
    int chPair = blockIdx.x * 8 + warp;
    int ch = chPair * 2 + (lane >> 4);
    int b = ch >> 11;
    int d = ch & 2047;
    int n = lane & 15;
    int rowBase = b * SEQ;

    const float* dtp = dtT + (size_t)d * NTOK + rowBase;
    const float* xsp = xsT + (size_t)d * NTOK + rowBase;
    const float* gp  = gT  + (size_t)d * NTOK + rowBase;
    const float* Bp  = bcT + (size_t)n * NTOK + rowBase;
    const float* Cp  = bcT + (size_t)(DSTATE + n) * NTOK + rowBase;
    float* yp = yT + (size_t)d * NTOK + rowBase;

    float a  = -expf(A_log[d * DSTATE + n]);
    float Dv = Dp[d];
    float s = 0.f;

    float4 dt4 = *reinterpret_cast<const float4*>(dtp);
    float4 xs4 = *reinterpret_cast<const float4*>(xsp);
    float4 g4  = *reinterpret_cast<const float4*>(gp);
    float4 B4  = *reinterpret_cast<const float4*>(Bp);
    float4 C4  = *reinterpret_cast<const float4*>(Cp);

    for (int t = 0; t < SEQ; t += 4) {
        float4 ndt, nxs, ng, nB, nC;
        if (t + 4 < SEQ) {
            ndt = *reinterpret_cast<const float4*>(dtp + t + 4);
            nxs = *reinterpret_cast<const float4*>(xsp + t + 4);
            ng  = *reinterpret_cast<const float4*>(gp + t + 4);
            nB  = *reinterpret_cast<const float4*>(Bp + t + 4);
            nC  = *reinterpret_cast<const float4*>(Cp + t + 4);
        }
        const float* dtv = &dt4.x; const float* xsv = &xs4.x;
        const float* gv = &g4.x; const float* Bv = &B4.x; const float* Cv = &C4.x;
        float4 yout;
        float* yv = &yout.x;
        #pragma unroll
        for (int q = 0; q < 4; q++) {
            float dA = __expf(dtv[q] * a);
            s = fmaf(dA, s, dtv[q] * xsv[q] * Bv[q]);
            float p = s * Cv[q];
            p += __shfl_xor_sync(0xffffffffu, p, 8);
            p += __shfl_xor_sync(0xffffffffu, p, 4);
            p += __shfl_xor_sync(0xffffffffu, p, 2);
            p += __shfl_xor_sync(0xffffffffu, p, 1);
            yv[q] = (p + Dv * xsv[q]) * gv[q];
        }
        if (n == 0)
            *reinterpret_cast<float4*>(yp + t) = yout;
        dt4 = ndt; xs4 = nxs; g4 = ng; B4 = nB; C4 = nC;
    }
}

// ---------------------------------------------------------------------------
// yT fp32 -> y fp16 (tiled transpose)
// ---------------------------------------------------------------------------
__global__ __launch_bounds__(256) void transpose_split(
    const float* __restrict__ yT, f16* __restrict__ yh)
{
    __shared__ float tile[32][33];
    int bx = blockIdx.x, by = blockIdx.y;
    int tx = threadIdx.x & 31, ty = threadIdx.x >> 5;
    #pragma unroll
    for (int j = 0; j < 32; j += 8) {
        int dd = by * 32 + ty + j;
        int tok = bx * 32 + tx;
        tile[ty + j][tx] = yT[(size_t)dd * NTOK + tok];
    }
    __syncthreads();
    #pragma unroll
    for (int j = 0; j < 32; j += 8) {
        int tok = bx * 32 + ty + j;
        int dd = by * 32 + tx;
        yh[(size_t)tok * DINNER + dd] = __float2half_rn(tile[tx][ty + j]);
    }
}

// ---------------------------------------------------------------------------
// Launch
// ---------------------------------------------------------------------------
extern "C" void kernel_launch(void* const* d_in, const int* in_sizes, int n_in,
                              void* d_out, int out_size)
{
    const float* x         = (const float*)d_in[0];
    const float* norm_w    = (const float*)d_in[1];
    const float* in_proj_w = (const float*)d_in[2];
    const float* conv_w    = (const float*)d_in[3];
    const float* conv_b    = (const float*)d_in[4];
    const float* x_proj_w  = (const float*)d_in[5];
    const float* dt_proj_w = (const float*)d_in[6];
    const float* dt_proj_b = (const float*)d_in[7];
    const float* A_log     = (const float*)d_in[8];
    const float* Dp        = (const float*)d_in[9];
    const float* out_proj_w= (const float*)d_in[10];
    float* out = (float*)d_out;

    float *pxz, *pxsT, *pgT, *pdtT, *pbcT, *pyT, *ppart;
    f16 *pwi, *pwx, *pwd, *pwo, *phh, *pxsh, *pxdh, *pyh;
    cudaGetSymbolAddress((void**)&pxz,  g_xz);
    cudaGetSymbolAddress((void**)&pxsT, g_xsT);
    cudaGetSymbolAddress((void**)&pgT,  g_gT);
    cudaGetSymbolAddress((void**)&pdtT, g_dtT);
    cudaGetSymbolAddress((void**)&pbcT, g_bcT);
    cudaGetSymbolAddress((void**)&pyT,  g_yT);
    cudaGetSymbolAddress((void**)&ppart,g_part);
    cudaGetSymbolAddress((void**)&pwi,  g_wi);
    cudaGetSymbolAddress((void**)&pwx,  g_wx);
    cudaGetSymbolAddress((void**)&pwd,  g_wd);
    cudaGetSymbolAddress((void**)&pwo,  g_wo);
    cudaGetSymbolAddress((void**)&phh,  g_hh);
    cudaGetSymbolAddress((void**)&pxsh, g_xsh);
    cudaGetSymbolAddress((void**)&pxdh, g_xdh);
    cudaGetSymbolAddress((void**)&pyh,  g_yh);

    cudaFuncSetAttribute(mma_gemm<0,0>, cudaFuncAttributeMaxDynamicSharedMemorySize, GEMM_SMEM);
    cudaFuncSetAttribute(mma_gemm<1,1>, cudaFuncAttributeMaxDynamicSharedMemorySize, GEMM_SMEM);
    cudaFuncSetAttribute(mma_gemm<2,0>, cudaFuncAttributeMaxDynamicSharedMemorySize, GEMM_SMEM);

    // 0) weight conversion (fp32 -> fp16)
    convert_w<<<(2*DINNER*DMODEL/4 + 255)/256, 256>>>(in_proj_w,  pwi, 2*DINNER*DMODEL/4);
    convert_w<<<(XPROJ_N*DINNER/4 + 255)/256, 256>>>(x_proj_w,   pwx, XPROJ_N*DINNER/4);
    convert_w<<<(DINNER*DTRANK/4 + 255)/256, 256>>>(dt_proj_w,  pwd, DINNER*DTRANK/4);
    convert_w<<<(DMODEL*DINNER/4 + 255)/256, 256>>>(out_proj_w, pwo, DMODEL*DINNER/4);

    // 1) RMSNorm
    rmsnorm_kernel<<<NTOK, 256>>>(x, norm_w, phh);

    // 2) in_proj
    {
        dim3 grid((2 * DINNER) / 128, NTOK / 128, 1);
        mma_gemm<0,0><<<grid, 256, GEMM_SMEM>>>(
            phh, DMODEL, pwi, DMODEL,
            pxz, 2 * DINNER, 2 * DINNER, DMODEL, 0, nullptr, nullptr, 0);
    }

    // 3) conv + silu (tiled, coalesced)
    {
        dim3 grid(DINNER / CD, NTOK / CT);
        conv_silu_kernel<<<grid, 256>>>(pxz, conv_w, conv_b,
                                        pxsh, pxsT, pgT);
    }

    // 4) x_proj split-K
    {
        dim3 grid(1, NTOK / 128, XSPLIT);
        mma_gemm<0,0><<<grid, 256, GEMM_SMEM>>>(
            pxsh, DINNER, pwx, DINNER,
            ppart, XPROJ_N, XPROJ_N, DINNER / XSPLIT,
            (long)NTOK * XPROJ_N, nullptr, nullptr, 0);
    }
    reduce_xproj<<<(NTOK * XPROJ_N + 255) / 256, 256>>>(ppart, pxdh, pbcT);

    // 5) dt_proj + softplus (coalesced transposed store)
    {
        dim3 grid(DINNER / 128, NTOK / 128, 1);
        mma_gemm<1,1><<<grid, 256, GEMM_SMEM>>>(
            pxdh, XPROJ_N, pwd, DTRANK,
            pdtT, NTOK, DINNER, DTRANK, 0, dt_proj_b, nullptr, 0);
    }

    // 6) scan -> yT
    scan_kernel<<<(BATCH * DINNER) / 16, 256>>>(pdtT, pxsT, pbcT, pgT,
                                                A_log, Dp, pyT);

    // 7) transpose y -> fp16
    {
        dim3 grid(NTOK / 32, DINNER / 32);
        transpose_split<<<grid, 256>>>(pyT, pyh);
    }

    // 8) out_proj + residual
    {
        dim3 grid(DMODEL / 128, NTOK / 128, 1);
        mma_gemm<2,0><<<grid, 256, GEMM_SMEM>>>(
            pyh, DINNER, pwo, DINNER,
            out, DMODEL, DMODEL, DINNER, 0, nullptr, x, DMODEL);
    }
}